// round 12
// baseline (speedup 1.0000x reference)
#include <cuda_runtime.h>
#include <math.h>

#define NN 50000
#define NE 800000
#define KIN 128
#define F 64
#define NF (NN*F)
#define SCAN_B 512
#define NBLK ((NN + SCAN_B - 1) / SCAN_B)   // 98

// ---- scratch (device globals; no allocation allowed) ----
__device__ __align__(16) float g_self[NF];
__device__ __align__(16) float g_bsum[NF];
__device__ __align__(16) float g_esum[NF];
__device__ __align__(16) float g_bmax[NF];
__device__ __align__(16) float g_emax[NF];
__device__ __align__(16) float g_segmax[NF];
__device__ __align__(16) float g_sumagg[NF];

__device__ int d_deg[NN];
__device__ int d_row[NN + 1];
__device__ int d_cur[NN];
__device__ int d_bsumI[NBLK];
__device__ int d_boff[NBLK];
__device__ int d_ei[NE];          // end ids sorted by begin id

// B (W_b) pre-packed in MMA fragment lane order, tf32-converted.
__device__ __align__(16) float d_B2[5 * 8 * 2 * 8 * 32 * 2];
// BN-folded W_u pre-packed in fragment lane order.
__device__ __align__(16) float d_W2[8 * 2 * 8 * 32 * 2];

__device__ __align__(16) float d_sum_s[64];
__device__ __align__(16) float d_ss_s[64];
__device__ __align__(16) float d_sum_g[128];
__device__ __align__(16) float d_ss_g[128];
__device__ __align__(16) float d_a_g[128];
__device__ __align__(16) float d_c_g[128];
__device__ __align__(16) float d_doff[64];
__device__ int   d_min_i;

// ---- monotone float<->int key ----
__device__ __forceinline__ int fkey(float f) {
    int i = __float_as_int(f);
    return i >= 0 ? i : (i ^ 0x7fffffff);
}
__device__ __forceinline__ float fdec(int k) {
    return __int_as_float(k >= 0 ? k : (k ^ 0x7fffffff));
}

// tf32 cvt: PTX requires .b32 destination register
__device__ __forceinline__ float to_tf32(float v) {
    unsigned r;
    asm("cvt.rna.tf32.f32 %0, %1;" : "=r"(r) : "f"(v));
    return __uint_as_float(r);
}
__device__ __forceinline__ float4 to_tf32_4(float4 v) {
    float4 r;
    r.x = to_tf32(v.x); r.y = to_tf32(v.y);
    r.z = to_tf32(v.z); r.w = to_tf32(v.w);
    return r;
}

// ---- K0: init small scratch ----
__global__ void k_init() {
    int i = blockIdx.x * blockDim.x + threadIdx.x;
    int stride = gridDim.x * blockDim.x;
    for (int j = i; j < NN; j += stride) d_deg[j] = 0;
    if (i < 64)  { d_sum_s[i] = 0.0f; d_ss_s[i] = 0.0f; }
    if (i < 128) { d_sum_g[i] = 0.0f; d_ss_g[i] = 0.0f; }
    if (i == 0)  d_min_i = INT_MAX;
}

// ---- CSR build ----
__global__ void k_deg(const int* __restrict__ b) {
    int i = blockIdx.x * blockDim.x + threadIdx.x;
    int stride = gridDim.x * blockDim.x;
    for (; i < NE; i += stride) atomicAdd(&d_deg[b[i]], 1);
}

// ---- pre-pack B into fragment lane order (tf32) ----
__global__ void k_prepB(const float* __restrict__ B) {  // [128,320]
    int idx = blockIdx.x * blockDim.x + threadIdx.x;    // 0..40959
    if (idx >= 5 * 8 * 2 * 8 * 32) return;
    int lane = idx & 31;
    int t = idx >> 5;
    int nbk = t & 7;  t >>= 3;
    int ks  = t & 1;  t >>= 1;
    int kc  = t & 7;  t >>= 3;
    int slice = t;                      // 0..4
    int g = lane >> 2, tig = lane & 3;
    int k = kc * 16 + ks * 8 + tig;
    int n = slice * 64 + nbk * 8 + g;
    float2 v;
    v.x = to_tf32(B[k * 320 + n]);
    v.y = to_tf32(B[(k + 4) * 320 + n]);
    *(float2*)&d_B2[idx * 2] = v;
}

__global__ void k_scan1() {
    __shared__ int sh[SCAN_B];
    int i = blockIdx.x * SCAN_B + threadIdx.x;
    sh[threadIdx.x] = (i < NN) ? d_deg[i] : 0;
    __syncthreads();
    for (int off = SCAN_B / 2; off; off >>= 1) {
        if (threadIdx.x < off) sh[threadIdx.x] += sh[threadIdx.x + off];
        __syncthreads();
    }
    if (threadIdx.x == 0) d_bsumI[blockIdx.x] = sh[0];
}

__global__ void k_scan2() {
    int t = threadIdx.x;
    int v = (t < NBLK) ? d_bsumI[t] : 0;
    int x = v;
    #pragma unroll
    for (int off = 1; off < 32; off <<= 1) {
        int y = __shfl_up_sync(0xffffffffu, x, off);
        if ((t & 31) >= off) x += y;
    }
    __shared__ int wt[4];
    if ((t & 31) == 31) wt[t >> 5] = x;
    __syncthreads();
    int add = 0;
    for (int w = 0; w < (t >> 5); w++) add += wt[w];
    x += add;
    if (t < NBLK) d_boff[t] = x - v;
    if (t == 0) d_row[NN] = NE;
}

__global__ void k_scan3() {
    int t = threadIdx.x;
    int lane = t & 31, w = t >> 5;
    int i = blockIdx.x * SCAN_B + t;
    int v = (i < NN) ? d_deg[i] : 0;
    int x = v;
    #pragma unroll
    for (int off = 1; off < 32; off <<= 1) {
        int y = __shfl_up_sync(0xffffffffu, x, off);
        if (lane >= off) x += y;
    }
    __shared__ int wt[16];
    if (lane == 31) wt[w] = x;
    __syncthreads();
    int add = d_boff[blockIdx.x];
    for (int k = 0; k < w; k++) add += wt[k];
    int excl = x - v + add;
    if (i < NN) { d_row[i] = excl; d_cur[i] = excl; }
}

__global__ void k_fill(const int* __restrict__ b, const int* __restrict__ e) {
    int i = blockIdx.x * blockDim.x + threadIdx.x;
    int stride = gridDim.x * blockDim.x;
    for (; i < NE; i += stride) {
        int pos = atomicAdd(&d_cur[b[i]], 1);
        d_ei[pos] = e[i];
    }
}

// ---- K1: GEMM1 tf32 mma.sync, A double-buffered, B from d_B2 (L2) ----
__global__ void __launch_bounds__(256, 2)
k_gemm1(const float* __restrict__ A,    // [NN,128]
        const float* __restrict__ bias) // [320]
{
    __shared__ __align__(16) float As[2][256][20];
    int tid = threadIdx.x;
    int lane = tid & 31, wid = tid >> 5;
    int wm = wid & 3, wn = wid >> 2;
    int g = lane >> 2, tig = lane & 3;
    int m0 = blockIdx.x * 256;
    int nb = blockIdx.y;

    float c[4][4][4];
    #pragma unroll
    for (int mt = 0; mt < 4; mt++)
        #pragma unroll
        for (int nt = 0; nt < 4; nt++)
            #pragma unroll
            for (int i = 0; i < 4; i++) c[mt][nt][i] = 0.0f;

    int frow = tid >> 2;
    int fc = (tid & 3) * 4;

    #pragma unroll
    for (int p = 0; p < 4; p++) {
        int row = p * 64 + frow;
        int gm = m0 + row;
        float4 v = make_float4(0.f, 0.f, 0.f, 0.f);
        if (gm < NN) v = *(const float4*)&A[gm * KIN + fc];
        *(float4*)&As[0][row][fc] = to_tf32_4(v);
    }
    __syncthreads();

    const float* b2base = &d_B2[(nb * 8) * 2 * 8 * 64];

    #pragma unroll
    for (int kci = 0; kci < 8; kci++) {
        int cur = kci & 1;
        float4 pf[4];
        if (kci < 7) {
            int kc = (kci + 1) * 16;
            #pragma unroll
            for (int p = 0; p < 4; p++) {
                int gm = m0 + p * 64 + frow;
                pf[p] = make_float4(0.f, 0.f, 0.f, 0.f);
                if (gm < NN) pf[p] = *(const float4*)&A[gm * KIN + kc + fc];
            }
        }

        #pragma unroll
        for (int ks = 0; ks < 2; ks++) {
            int kk = ks * 8 + tig;
            unsigned af[4][4];
            #pragma unroll
            for (int mt = 0; mt < 4; mt++) {
                int mr = wm * 64 + mt * 16;
                af[mt][0] = __float_as_uint(As[cur][mr + g][kk]);
                af[mt][1] = __float_as_uint(As[cur][mr + g + 8][kk]);
                af[mt][2] = __float_as_uint(As[cur][mr + g][kk + 4]);
                af[mt][3] = __float_as_uint(As[cur][mr + g + 8][kk + 4]);
            }
            #pragma unroll
            for (int nt = 0; nt < 4; nt++) {
                int nbk = wn * 4 + nt;
                float2 bf = *(const float2*)&b2base[(((kci * 2) + ks) * 8 + nbk) * 64 + lane * 2];
                unsigned b0 = __float_as_uint(bf.x);
                unsigned b1 = __float_as_uint(bf.y);
                #pragma unroll
                for (int mt = 0; mt < 4; mt++) {
                    asm volatile(
                        "mma.sync.aligned.m16n8k8.row.col.f32.tf32.tf32.f32 "
                        "{%0,%1,%2,%3}, {%4,%5,%6,%7}, {%8,%9}, {%0,%1,%2,%3};"
                        : "+f"(c[mt][nt][0]), "+f"(c[mt][nt][1]),
                          "+f"(c[mt][nt][2]), "+f"(c[mt][nt][3])
                        : "r"(af[mt][0]), "r"(af[mt][1]), "r"(af[mt][2]), "r"(af[mt][3]),
                          "r"(b0), "r"(b1));
                }
            }
        }

        if (kci < 7) {
            #pragma unroll
            for (int p = 0; p < 4; p++)
                *(float4*)&As[cur ^ 1][p * 64 + frow][fc] = to_tf32_4(pf[p]);
        }
        __syncthreads();
    }

    int n0 = nb * 64;
    float* outp = (nb == 0) ? g_self : (nb == 1) ? g_bsum :
                  (nb == 2) ? g_esum : (nb == 3) ? g_bmax : g_emax;
    #pragma unroll
    for (int mt = 0; mt < 4; mt++) {
        #pragma unroll
        for (int nt = 0; nt < 4; nt++) {
            int col = wn * 32 + nt * 8 + tig * 2;
            float bx = bias[n0 + col], by = bias[n0 + col + 1];
            int r0 = m0 + wm * 64 + mt * 16 + g;
            if (r0 < NN) {
                float2 o; o.x = c[mt][nt][0] + bx; o.y = c[mt][nt][1] + by;
                *(float2*)&outp[r0 * 64 + col] = o;
            }
            int r1 = r0 + 8;
            if (r1 < NN) {
                float2 o; o.x = c[mt][nt][2] + bx; o.y = c[mt][nt][3] + by;
                *(float2*)&outp[r1 * 64 + col] = o;
            }
        }
    }
}

// ---- pass A: per-node segment max + edge-BN stats + global min (4-edge unroll) ----
__global__ void k_edgeA() {
    __shared__ float s_acc[128];
    __shared__ int s_min;
    int tid = threadIdx.x;
    int lane = tid & 31;
    if (tid < 128) s_acc[tid] = 0.0f;
    if (tid == 0) s_min = INT_MAX;
    __syncthreads();

    int warp = (blockIdx.x * blockDim.x + tid) >> 5;
    int nwarp = (gridDim.x * blockDim.x) >> 5;
    float asx = 0.f, asy = 0.f, aqx = 0.f, aqy = 0.f;
    float lmin = INFINITY;

    for (int n = warp; n < NN; n += nwarp) {
        int beg = d_row[n], end = d_row[n + 1];
        float2 bs = *(const float2*)&g_bsum[n * 64 + 2 * lane];
        float2 bm = *(const float2*)&g_bmax[n * 64 + 2 * lane];
        float mx = -INFINITY, my = -INFINITY;
        int e = beg;
        for (; e + 3 < end; e += 4) {
            int ei0 = d_ei[e], ei1 = d_ei[e + 1], ei2 = d_ei[e + 2], ei3 = d_ei[e + 3];
            float2 es0 = *(const float2*)&g_esum[ei0 * 64 + 2 * lane];
            float2 es1 = *(const float2*)&g_esum[ei1 * 64 + 2 * lane];
            float2 es2 = *(const float2*)&g_esum[ei2 * 64 + 2 * lane];
            float2 es3 = *(const float2*)&g_esum[ei3 * 64 + 2 * lane];
            float2 em0 = *(const float2*)&g_emax[ei0 * 64 + 2 * lane];
            float2 em1 = *(const float2*)&g_emax[ei1 * 64 + 2 * lane];
            float2 em2 = *(const float2*)&g_emax[ei2 * 64 + 2 * lane];
            float2 em3 = *(const float2*)&g_emax[ei3 * 64 + 2 * lane];
            float sx0 = bs.x + es0.x, sy0 = bs.y + es0.y;
            float sx1 = bs.x + es1.x, sy1 = bs.y + es1.y;
            float sx2 = bs.x + es2.x, sy2 = bs.y + es2.y;
            float sx3 = bs.x + es3.x, sy3 = bs.y + es3.y;
            asx += (sx0 + sx1) + (sx2 + sx3);
            asy += (sy0 + sy1) + (sy2 + sy3);
            aqx += (sx0 * sx0 + sx1 * sx1) + (sx2 * sx2 + sx3 * sx3);
            aqy += (sy0 * sy0 + sy1 * sy1) + (sy2 * sy2 + sy3 * sy3);
            float m0x = bm.x + em0.x, m0y = bm.y + em0.y;
            float m1x = bm.x + em1.x, m1y = bm.y + em1.y;
            float m2x = bm.x + em2.x, m2y = bm.y + em2.y;
            float m3x = bm.x + em3.x, m3y = bm.y + em3.y;
            mx = fmaxf(mx, fmaxf(fmaxf(m0x, m1x), fmaxf(m2x, m3x)));
            my = fmaxf(my, fmaxf(fmaxf(m0y, m1y), fmaxf(m2y, m3y)));
            lmin = fminf(lmin, fminf(fminf(fminf(m0x, m0y), fminf(m1x, m1y)),
                                     fminf(fminf(m2x, m2y), fminf(m3x, m3y))));
        }
        for (; e < end; e++) {
            int ei0 = d_ei[e];
            float2 es0 = *(const float2*)&g_esum[ei0 * 64 + 2 * lane];
            float2 em0 = *(const float2*)&g_emax[ei0 * 64 + 2 * lane];
            float sx0 = bs.x + es0.x, sy0 = bs.y + es0.y;
            asx += sx0; asy += sy0;
            aqx += sx0 * sx0; aqy += sy0 * sy0;
            float m0x = bm.x + em0.x, m0y = bm.y + em0.y;
            mx = fmaxf(mx, m0x);
            my = fmaxf(my, m0y);
            lmin = fminf(lmin, fminf(m0x, m0y));
        }
        float2 o; o.x = mx; o.y = my;
        *(float2*)&g_segmax[n * 64 + 2 * lane] = o;
    }

    atomicAdd(&s_acc[2 * lane], asx);
    atomicAdd(&s_acc[2 * lane + 1], asy);
    atomicAdd(&s_acc[64 + 2 * lane], aqx);
    atomicAdd(&s_acc[64 + 2 * lane + 1], aqy);
    #pragma unroll
    for (int off = 16; off; off >>= 1)
        lmin = fminf(lmin, __shfl_xor_sync(0xffffffffu, lmin, off));
    if (lane == 0) atomicMin(&s_min, fkey(lmin));
    __syncthreads();
    if (tid < 64) {
        atomicAdd(&d_sum_s[tid], s_acc[tid]);
        atomicAdd(&d_ss_s[tid], s_acc[64 + tid]);
    }
    if (tid == 0) atomicMin(&d_min_i, s_min);
}

// ---- pass B: relu(bn(ef_sum)) per-node sum + node-BN stats (4-edge unroll) ----
__global__ void k_edgeB(const float* __restrict__ gamma,
                        const float* __restrict__ beta) {
    __shared__ float s_acc[128];
    int tid = threadIdx.x;
    int lane = tid & 31;
    if (tid < 128) s_acc[tid] = 0.0f;
    __syncthreads();

    int f0 = 2 * lane, f1 = 2 * lane + 1;
    float mux = d_sum_s[f0] / (float)NE;
    float muy = d_sum_s[f1] / (float)NE;
    float isx = rsqrtf(d_ss_s[f0] / (float)NE - mux * mux + 1e-5f);
    float isy = rsqrtf(d_ss_s[f1] / (float)NE - muy * muy + 1e-5f);
    float ax = isx * gamma[f0], ay = isy * gamma[f1];
    float cx = beta[f0] - mux * ax, cy = beta[f1] - muy * ay;

    int warp = (blockIdx.x * blockDim.x + tid) >> 5;
    int nwarp = (gridDim.x * blockDim.x) >> 5;
    float nsx = 0.f, nsy = 0.f, nqx = 0.f, nqy = 0.f;

    for (int n = warp; n < NN; n += nwarp) {
        int beg = d_row[n], end = d_row[n + 1];
        float2 bs = *(const float2*)&g_bsum[n * 64 + f0];
        float accx = 0.f, accy = 0.f;
        int e = beg;
        for (; e + 3 < end; e += 4) {
            int ei0 = d_ei[e], ei1 = d_ei[e + 1], ei2 = d_ei[e + 2], ei3 = d_ei[e + 3];
            float2 es0 = *(const float2*)&g_esum[ei0 * 64 + f0];
            float2 es1 = *(const float2*)&g_esum[ei1 * 64 + f0];
            float2 es2 = *(const float2*)&g_esum[ei2 * 64 + f0];
            float2 es3 = *(const float2*)&g_esum[ei3 * 64 + f0];
            accx += (fmaxf(0.f, fmaf(bs.x + es0.x, ax, cx))
                   + fmaxf(0.f, fmaf(bs.x + es1.x, ax, cx)))
                  + (fmaxf(0.f, fmaf(bs.x + es2.x, ax, cx))
                   + fmaxf(0.f, fmaf(bs.x + es3.x, ax, cx)));
            accy += (fmaxf(0.f, fmaf(bs.y + es0.y, ay, cy))
                   + fmaxf(0.f, fmaf(bs.y + es1.y, ay, cy)))
                  + (fmaxf(0.f, fmaf(bs.y + es2.y, ay, cy))
                   + fmaxf(0.f, fmaf(bs.y + es3.y, ay, cy)));
        }
        for (; e < end; e++) {
            int ei0 = d_ei[e];
            float2 es0 = *(const float2*)&g_esum[ei0 * 64 + f0];
            accx += fmaxf(0.f, fmaf(bs.x + es0.x, ax, cx));
            accy += fmaxf(0.f, fmaf(bs.y + es0.y, ay, cy));
        }
        float2 o; o.x = accx; o.y = accy;
        *(float2*)&g_sumagg[n * 64 + f0] = o;
        nsx += accx; nsy += accy;
        nqx += accx * accx; nqy += accy * accy;
    }

    atomicAdd(&s_acc[f0], nsx);
    atomicAdd(&s_acc[f1], nsy);
    atomicAdd(&s_acc[64 + f0], nqx);
    atomicAdd(&s_acc[64 + f1], nqy);
    __syncthreads();
    if (tid < 64) {
        atomicAdd(&d_sum_g[64 + tid], s_acc[tid]);
        atomicAdd(&d_ss_g[64 + tid], s_acc[64 + tid]);
    }
}

// ---- K5: empty-segment fix + node-BN stats for segmax half ----
__global__ void k_node() {
    __shared__ float s_acc[128];
    int tid = threadIdx.x;
    int lane = tid & 31;
    if (tid < 128) s_acc[tid] = 0.0f;
    __syncthreads();

    int f0 = 2 * lane;
    float minv = fdec(d_min_i);
    int warp = (blockIdx.x * blockDim.x + tid) >> 5;
    int nwarp = (gridDim.x * blockDim.x) >> 5;
    float nsx = 0.f, nsy = 0.f, nqx = 0.f, nqy = 0.f;
    for (int n = warp; n < NN; n += nwarp) {
        float2 v = *(const float2*)&g_segmax[n * 64 + f0];
        if (v.x == -INFINITY) {
            v.x = minv; v.y = minv;
            *(float2*)&g_segmax[n * 64 + f0] = v;
        }
        nsx += v.x; nsy += v.y;
        nqx += v.x * v.x; nqy += v.y * v.y;
    }
    atomicAdd(&s_acc[f0], nsx);
    atomicAdd(&s_acc[f0 + 1], nsy);
    atomicAdd(&s_acc[64 + f0], nqx);
    atomicAdd(&s_acc[64 + f0 + 1], nqy);
    __syncthreads();
    if (tid < 64) {
        atomicAdd(&d_sum_g[tid], s_acc[tid]);
        atomicAdd(&d_ss_g[tid], s_acc[64 + tid]);
    }
}

// ---- K6: finalize node-BN; pack BN-folded W_u into fragment order + doff ----
__global__ void k_fin_g(const float* __restrict__ gamma_u,
                        const float* __restrict__ beta_u,
                        const float* __restrict__ W_u) {
    int t = threadIdx.x;  // 256
    if (t < 128) {
        float mu = d_sum_g[t] / (float)NN;
        float var = d_ss_g[t] / (float)NN - mu * mu;
        float a = rsqrtf(var + 1e-5f) * gamma_u[t];
        d_a_g[t] = a;
        d_c_g[t] = beta_u[t] - mu * a;
    }
    __syncthreads();
    for (int e = t; e < 8 * 2 * 8 * 32; e += 256) {
        int lane = e & 31;
        int t2 = e >> 5;
        int nbk = t2 & 7;
        int ks = (t2 >> 3) & 1;
        int kc = t2 >> 4;
        int g = lane >> 2, tig = lane & 3;
        int k = kc * 16 + ks * 8 + tig;
        int n = nbk * 8 + g;
        float2 v;
        v.x = to_tf32(d_a_g[k] * W_u[k * 64 + n]);
        v.y = to_tf32(d_a_g[k + 4] * W_u[(k + 4) * 64 + n]);
        *(float2*)&d_W2[e * 2] = v;
    }
    if (t < 64) {
        float acc = 0.f;
        for (int k = 0; k < 128; k++) acc += d_c_g[k] * W_u[k * 64 + t];
        d_doff[t] = acc;
    }
}

// ---- K7: GEMM2 tf32 mma: out = self + relu([segmax|sumagg] @ W' + doff) ----
__global__ void __launch_bounds__(256, 2)
k_final(float* __restrict__ out) {
    __shared__ __align__(16) float As[2][256][20];
    int tid = threadIdx.x;
    int lane = tid & 31, wid = tid >> 5;
    int wm = wid & 3, wn = wid >> 2;
    int g = lane >> 2, tig = lane & 3;
    int m0 = blockIdx.x * 256;

    float c[4][4][4];
    #pragma unroll
    for (int mt = 0; mt < 4; mt++)
        #pragma unroll
        for (int nt = 0; nt < 4; nt++)
            #pragma unroll
            for (int i = 0; i < 4; i++) c[mt][nt][i] = 0.0f;

    int frow = tid >> 2;
    int fc = (tid & 3) * 4;

    #pragma unroll
    for (int p = 0; p < 4; p++) {
        int gm = m0 + p * 64 + frow;
        float4 v = make_float4(0.f, 0.f, 0.f, 0.f);
        if (gm < NN) v = *(const float4*)&g_segmax[gm * 64 + fc];
        *(float4*)&As[0][p * 64 + frow][fc] = to_tf32_4(v);
    }
    __syncthreads();

    #pragma unroll
    for (int kci = 0; kci < 8; kci++) {
        int cur = kci & 1;
        float4 pf[4];
        if (kci < 7) {
            int kg = (kci + 1) * 16 + fc;
            const float* src = (kg < 64) ? g_segmax : g_sumagg;
            int off = (kg < 64) ? kg : (kg - 64);
            #pragma unroll
            for (int p = 0; p < 4; p++) {
                int gm = m0 + p * 64 + frow;
                pf[p] = make_float4(0.f, 0.f, 0.f, 0.f);
                if (gm < NN) pf[p] = *(const float4*)&src[gm * 64 + off];
            }
        }

        #pragma unroll
        for (int ks = 0; ks < 2; ks++) {
            int kk = ks * 8 + tig;
            unsigned af[4][4];
            #pragma unroll
            for (int mt = 0; mt < 4; mt++) {
                int mr = wm * 64 + mt * 16;
                af[mt][0] = __float_as_uint(As[cur][mr + g][kk]);
                af[mt][1] = __float_as_uint(As[cur][mr + g + 8][kk]);
                af[mt][2] = __float_as_uint(As[cur][mr + g][kk + 4]);
                af[mt][3] = __float_as_uint(As[cur][mr + g + 8][kk + 4]);
            }
            #pragma unroll
            for (int nt = 0; nt < 4; nt++) {
                int nbk = wn * 4 + nt;
                float2 bf = *(const float2*)&d_W2[(((kci * 2) + ks) * 8 + nbk) * 64 + lane * 2];
                unsigned b0 = __float_as_uint(bf.x);
                unsigned b1 = __float_as_uint(bf.y);
                #pragma unroll
                for (int mt = 0; mt < 4; mt++) {
                    asm volatile(
                        "mma.sync.aligned.m16n8k8.row.col.f32.tf32.tf32.f32 "
                        "{%0,%1,%2,%3}, {%4,%5,%6,%7}, {%8,%9}, {%0,%1,%2,%3};"
                        : "+f"(c[mt][nt][0]), "+f"(c[mt][nt][1]),
                          "+f"(c[mt][nt][2]), "+f"(c[mt][nt][3])
                        : "r"(af[mt][0]), "r"(af[mt][1]), "r"(af[mt][2]), "r"(af[mt][3]),
                          "r"(b0), "r"(b1));
                }
            }
        }

        if (kci < 7) {
            #pragma unroll
            for (int p = 0; p < 4; p++)
                *(float4*)&As[cur ^ 1][p * 64 + frow][fc] = to_tf32_4(pf[p]);
        }
        __syncthreads();
    }

    #pragma unroll
    for (int mt = 0; mt < 4; mt++) {
        #pragma unroll
        for (int nt = 0; nt < 4; nt++) {
            int col = wn * 32 + nt * 8 + tig * 2;
            float dx = d_doff[col], dy = d_doff[col + 1];
            int r0 = m0 + wm * 64 + mt * 16 + g;
            if (r0 < NN) {
                float2 sf = *(const float2*)&g_self[r0 * 64 + col];
                float2 o;
                o.x = sf.x + fmaxf(0.f, c[mt][nt][0] + dx);
                o.y = sf.y + fmaxf(0.f, c[mt][nt][1] + dy);
                *(float2*)&out[r0 * 64 + col] = o;
            }
            int r1 = r0 + 8;
            if (r1 < NN) {
                float2 sf = *(const float2*)&g_self[r1 * 64 + col];
                float2 o;
                o.x = sf.x + fmaxf(0.f, c[mt][nt][2] + dx);
                o.y = sf.y + fmaxf(0.f, c[mt][nt][3] + dy);
                *(float2*)&out[r1 * 64 + col] = o;
            }
        }
    }
}

extern "C" void kernel_launch(void* const* d_in, const int* in_sizes, int n_in,
                              void* d_out, int out_size) {
    const float* n_feat  = (const float*)d_in[0];
    const int*   eidx    = (const int*)d_in[1];
    const float* W_b     = (const float*)d_in[2];
    const float* b_b     = (const float*)d_in[3];
    const float* gamma_g = (const float*)d_in[4];
    const float* beta_g  = (const float*)d_in[5];
    const float* gamma_u = (const float*)d_in[6];
    const float* beta_u  = (const float*)d_in[7];
    const float* W_u     = (const float*)d_in[8];
    float* out           = (float*)d_out;

    const int* begin_ids = eidx;
    const int* end_ids   = eidx + NE;

    static cudaStream_t s1 = 0;
    static cudaEvent_t evFork = 0, evJoin = 0, evFork2 = 0, evJoin2 = 0;
    if (!s1) {
        cudaStreamCreateWithFlags(&s1, cudaStreamNonBlocking);
        cudaEventCreateWithFlags(&evFork, cudaEventDisableTiming);
        cudaEventCreateWithFlags(&evJoin, cudaEventDisableTiming);
        cudaEventCreateWithFlags(&evFork2, cudaEventDisableTiming);
        cudaEventCreateWithFlags(&evJoin2, cudaEventDisableTiming);
    }

    // fork: GEMM chain on s1 (single 5-slice launch, round-10 structure)
    cudaEventRecord(evFork, 0);
    cudaStreamWaitEvent(s1, evFork, 0);
    k_prepB<<<160, 256, 0, s1>>>(W_b);
    dim3 g1((NN + 255) / 256, 5);
    k_gemm1<<<g1, 256, 0, s1>>>(n_feat, b_b);

    k_init<<<256, 256>>>();
    k_deg<<<1184, 256>>>(begin_ids);
    k_scan1<<<NBLK, SCAN_B>>>();
    k_scan2<<<1, 128>>>();
    k_scan3<<<NBLK, SCAN_B>>>();
    k_fill<<<1184, 256>>>(begin_ids, end_ids);

    // join: edgeA needs GEMM outputs and CSR
    cudaEventRecord(evJoin, s1);
    cudaStreamWaitEvent(0, evJoin, 0);
    k_edgeA<<<1184, 256>>>();

    // fork 2: k_node (needs only edgeA) overlaps edgeB (disjoint d_sum_g halves)
    cudaEventRecord(evFork2, 0);
    cudaStreamWaitEvent(s1, evFork2, 0);
    k_node<<<1184, 256, 0, s1>>>();

    k_edgeB<<<1184, 256>>>(gamma_g, beta_g);

    cudaEventRecord(evJoin2, s1);
    cudaStreamWaitEvent(0, evJoin2, 0);
    k_fin_g<<<1, 256>>>(gamma_u, beta_u, W_u);
    k_final<<<(NN + 255) / 256, 256>>>(out);
}

// round 13
// speedup vs baseline: 1.0417x; 1.0417x over previous
#include <cuda_runtime.h>
#include <math.h>

#define NN 50000
#define NE 800000
#define KIN 128
#define F 64
#define NF (NN*F)
#define SCAN_B 512
#define NBLK ((NN + SCAN_B - 1) / SCAN_B)   // 98

// ---- scratch (device globals; no allocation allowed) ----
__device__ __align__(16) float g_self[NF];
__device__ __align__(16) float g_bsum[NF];
__device__ __align__(16) float g_esum[NF];
__device__ __align__(16) float g_bmax[NF];
__device__ __align__(16) float g_emax[NF];
__device__ __align__(16) float g_segmax[NF];
__device__ __align__(16) float g_sumagg[NF];

__device__ int d_deg[NN];
__device__ int d_row[NN + 1];
__device__ int d_cur[NN];
__device__ int d_bsumI[NBLK];
__device__ int d_boff[NBLK];
__device__ int d_ei[NE];          // end ids sorted by begin id

// B (W_b) pre-packed in MMA fragment lane order, tf32-converted.
__device__ __align__(16) float d_B2[5 * 8 * 2 * 8 * 32 * 2];
// BN-folded W_u pre-packed in fragment lane order (single 64-col slice).
__device__ __align__(16) float d_W2[8 * 2 * 8 * 32 * 2];

__device__ __align__(16) float d_sum_s[64];
__device__ __align__(16) float d_ss_s[64];
__device__ __align__(16) float d_sum_g[128];
__device__ __align__(16) float d_ss_g[128];
__device__ __align__(16) float d_a_g[128];
__device__ __align__(16) float d_c_g[128];
__device__ __align__(16) float d_doff[64];
__device__ int   d_min_i;

// ---- monotone float<->int key ----
__device__ __forceinline__ int fkey(float f) {
    int i = __float_as_int(f);
    return i >= 0 ? i : (i ^ 0x7fffffff);
}
__device__ __forceinline__ float fdec(int k) {
    return __int_as_float(k >= 0 ? k : (k ^ 0x7fffffff));
}

// tf32 cvt: PTX requires .b32 destination register
__device__ __forceinline__ float to_tf32(float v) {
    unsigned r;
    asm("cvt.rna.tf32.f32 %0, %1;" : "=r"(r) : "f"(v));
    return __uint_as_float(r);
}
__device__ __forceinline__ float4 to_tf32_4(float4 v) {
    float4 r;
    r.x = to_tf32(v.x); r.y = to_tf32(v.y);
    r.z = to_tf32(v.z); r.w = to_tf32(v.w);
    return r;
}

// ---- K0: init small scratch ----
__global__ void k_init() {
    int i = blockIdx.x * blockDim.x + threadIdx.x;
    int stride = gridDim.x * blockDim.x;
    for (int j = i; j < NN; j += stride) d_deg[j] = 0;
    if (i < 64)  { d_sum_s[i] = 0.0f; d_ss_s[i] = 0.0f; }
    if (i < 128) { d_sum_g[i] = 0.0f; d_ss_g[i] = 0.0f; }
    if (i == 0)  d_min_i = INT_MAX;
}

// ---- CSR build ----
__global__ void k_deg(const int* __restrict__ b) {
    int i = blockIdx.x * blockDim.x + threadIdx.x;
    int stride = gridDim.x * blockDim.x;
    for (; i < NE; i += stride) atomicAdd(&d_deg[b[i]], 1);
}

// ---- pre-pack B into fragment lane order (tf32) ----
__global__ void k_prepB(const float* __restrict__ B) {  // [128,320]
    int idx = blockIdx.x * blockDim.x + threadIdx.x;    // 0..40959
    if (idx >= 5 * 8 * 2 * 8 * 32) return;
    int lane = idx & 31;
    int t = idx >> 5;
    int nbk = t & 7;  t >>= 3;
    int ks  = t & 1;  t >>= 1;
    int kc  = t & 7;  t >>= 3;
    int slice = t;                      // 0..4
    int g = lane >> 2, tig = lane & 3;
    int k = kc * 16 + ks * 8 + tig;
    int n = slice * 64 + nbk * 8 + g;
    float2 v;
    v.x = to_tf32(B[k * 320 + n]);
    v.y = to_tf32(B[(k + 4) * 320 + n]);
    *(float2*)&d_B2[idx * 2] = v;
}

__global__ void k_scan1() {
    __shared__ int sh[SCAN_B];
    int i = blockIdx.x * SCAN_B + threadIdx.x;
    sh[threadIdx.x] = (i < NN) ? d_deg[i] : 0;
    __syncthreads();
    for (int off = SCAN_B / 2; off; off >>= 1) {
        if (threadIdx.x < off) sh[threadIdx.x] += sh[threadIdx.x + off];
        __syncthreads();
    }
    if (threadIdx.x == 0) d_bsumI[blockIdx.x] = sh[0];
}

__global__ void k_scan2() {
    int t = threadIdx.x;
    int v = (t < NBLK) ? d_bsumI[t] : 0;
    int x = v;
    #pragma unroll
    for (int off = 1; off < 32; off <<= 1) {
        int y = __shfl_up_sync(0xffffffffu, x, off);
        if ((t & 31) >= off) x += y;
    }
    __shared__ int wt[4];
    if ((t & 31) == 31) wt[t >> 5] = x;
    __syncthreads();
    int add = 0;
    for (int w = 0; w < (t >> 5); w++) add += wt[w];
    x += add;
    if (t < NBLK) d_boff[t] = x - v;
    if (t == 0) d_row[NN] = NE;
}

__global__ void k_scan3() {
    int t = threadIdx.x;
    int lane = t & 31, w = t >> 5;
    int i = blockIdx.x * SCAN_B + t;
    int v = (i < NN) ? d_deg[i] : 0;
    int x = v;
    #pragma unroll
    for (int off = 1; off < 32; off <<= 1) {
        int y = __shfl_up_sync(0xffffffffu, x, off);
        if (lane >= off) x += y;
    }
    __shared__ int wt[16];
    if (lane == 31) wt[w] = x;
    __syncthreads();
    int add = d_boff[blockIdx.x];
    for (int k = 0; k < w; k++) add += wt[k];
    int excl = x - v + add;
    if (i < NN) { d_row[i] = excl; d_cur[i] = excl; }
}

__global__ void k_fill(const int* __restrict__ b, const int* __restrict__ e) {
    int i = blockIdx.x * blockDim.x + threadIdx.x;
    int stride = gridDim.x * blockDim.x;
    for (; i < NE; i += stride) {
        int pos = atomicAdd(&d_cur[b[i]], 1);
        d_ei[pos] = e[i];
    }
}

// ---- K1: GEMM1 tf32 mma.sync, A double-buffered in smem, B from d_B2 (L2) ----
__global__ void __launch_bounds__(256, 2)
k_gemm1(const float* __restrict__ A,    // [NN,128]
        const float* __restrict__ bias) // [320]
{
    __shared__ __align__(16) float As[2][256][20];
    int tid = threadIdx.x;
    int lane = tid & 31, wid = tid >> 5;
    int wm = wid & 3, wn = wid >> 2;
    int g = lane >> 2, tig = lane & 3;
    int m0 = blockIdx.x * 256;
    int nb = blockIdx.y;

    float c[4][4][4];
    #pragma unroll
    for (int mt = 0; mt < 4; mt++)
        #pragma unroll
        for (int nt = 0; nt < 4; nt++)
            #pragma unroll
            for (int i = 0; i < 4; i++) c[mt][nt][i] = 0.0f;

    int frow = tid >> 2;
    int fc = (tid & 3) * 4;

    #pragma unroll
    for (int p = 0; p < 4; p++) {
        int row = p * 64 + frow;
        int gm = m0 + row;
        float4 v = make_float4(0.f, 0.f, 0.f, 0.f);
        if (gm < NN) v = *(const float4*)&A[gm * KIN + fc];
        *(float4*)&As[0][row][fc] = to_tf32_4(v);
    }
    __syncthreads();

    const float* b2base = &d_B2[(nb * 8) * 2 * 8 * 64];

    #pragma unroll
    for (int kci = 0; kci < 8; kci++) {
        int cur = kci & 1;
        float4 pf[4];
        if (kci < 7) {
            int kc = (kci + 1) * 16;
            #pragma unroll
            for (int p = 0; p < 4; p++) {
                int gm = m0 + p * 64 + frow;
                pf[p] = make_float4(0.f, 0.f, 0.f, 0.f);
                if (gm < NN) pf[p] = *(const float4*)&A[gm * KIN + kc + fc];
            }
        }

        #pragma unroll
        for (int ks = 0; ks < 2; ks++) {
            int kk = ks * 8 + tig;
            unsigned af[4][4];
            #pragma unroll
            for (int mt = 0; mt < 4; mt++) {
                int mr = wm * 64 + mt * 16;
                af[mt][0] = __float_as_uint(As[cur][mr + g][kk]);
                af[mt][1] = __float_as_uint(As[cur][mr + g + 8][kk]);
                af[mt][2] = __float_as_uint(As[cur][mr + g][kk + 4]);
                af[mt][3] = __float_as_uint(As[cur][mr + g + 8][kk + 4]);
            }
            #pragma unroll
            for (int nt = 0; nt < 4; nt++) {
                int nbk = wn * 4 + nt;
                float2 bf = *(const float2*)&b2base[(((kci * 2) + ks) * 8 + nbk) * 64 + lane * 2];
                unsigned b0 = __float_as_uint(bf.x);
                unsigned b1 = __float_as_uint(bf.y);
                #pragma unroll
                for (int mt = 0; mt < 4; mt++) {
                    asm volatile(
                        "mma.sync.aligned.m16n8k8.row.col.f32.tf32.tf32.f32 "
                        "{%0,%1,%2,%3}, {%4,%5,%6,%7}, {%8,%9}, {%0,%1,%2,%3};"
                        : "+f"(c[mt][nt][0]), "+f"(c[mt][nt][1]),
                          "+f"(c[mt][nt][2]), "+f"(c[mt][nt][3])
                        : "r"(af[mt][0]), "r"(af[mt][1]), "r"(af[mt][2]), "r"(af[mt][3]),
                          "r"(b0), "r"(b1));
                }
            }
        }

        if (kci < 7) {
            #pragma unroll
            for (int p = 0; p < 4; p++)
                *(float4*)&As[cur ^ 1][p * 64 + frow][fc] = to_tf32_4(pf[p]);
        }
        __syncthreads();
    }

    int n0 = nb * 64;
    float* outp = (nb == 0) ? g_self : (nb == 1) ? g_bsum :
                  (nb == 2) ? g_esum : (nb == 3) ? g_bmax : g_emax;
    #pragma unroll
    for (int mt = 0; mt < 4; mt++) {
        #pragma unroll
        for (int nt = 0; nt < 4; nt++) {
            int col = wn * 32 + nt * 8 + tig * 2;
            float bx = bias[n0 + col], by = bias[n0 + col + 1];
            int r0 = m0 + wm * 64 + mt * 16 + g;
            if (r0 < NN) {
                float2 o; o.x = c[mt][nt][0] + bx; o.y = c[mt][nt][1] + by;
                *(float2*)&outp[r0 * 64 + col] = o;
            }
            int r1 = r0 + 8;
            if (r1 < NN) {
                float2 o; o.x = c[mt][nt][2] + bx; o.y = c[mt][nt][3] + by;
                *(float2*)&outp[r1 * 64 + col] = o;
            }
        }
    }
}

// ---- pass A: per-node segment max + edge-BN stats + global min (2-edge unroll) ----
__global__ void k_edgeA() {
    __shared__ float s_acc[128];
    __shared__ int s_min;
    int tid = threadIdx.x;
    int lane = tid & 31;
    if (tid < 128) s_acc[tid] = 0.0f;
    if (tid == 0) s_min = INT_MAX;
    __syncthreads();

    int warp = (blockIdx.x * blockDim.x + tid) >> 5;
    int nwarp = (gridDim.x * blockDim.x) >> 5;
    float asx = 0.f, asy = 0.f, aqx = 0.f, aqy = 0.f;
    float lmin = INFINITY;

    for (int n = warp; n < NN; n += nwarp) {
        int beg = d_row[n], end = d_row[n + 1];
        float2 bs = *(const float2*)&g_bsum[n * 64 + 2 * lane];
        float2 bm = *(const float2*)&g_bmax[n * 64 + 2 * lane];
        float mx = -INFINITY, my = -INFINITY;
        int e = beg;
        for (; e + 1 < end; e += 2) {
            int ei0 = d_ei[e], ei1 = d_ei[e + 1];
            float2 es0 = *(const float2*)&g_esum[ei0 * 64 + 2 * lane];
            float2 em0 = *(const float2*)&g_emax[ei0 * 64 + 2 * lane];
            float2 es1 = *(const float2*)&g_esum[ei1 * 64 + 2 * lane];
            float2 em1 = *(const float2*)&g_emax[ei1 * 64 + 2 * lane];
            float sx0 = bs.x + es0.x, sy0 = bs.y + es0.y;
            float sx1 = bs.x + es1.x, sy1 = bs.y + es1.y;
            asx += sx0 + sx1; asy += sy0 + sy1;
            aqx += sx0 * sx0 + sx1 * sx1;
            aqy += sy0 * sy0 + sy1 * sy1;
            float m0x = bm.x + em0.x, m0y = bm.y + em0.y;
            float m1x = bm.x + em1.x, m1y = bm.y + em1.y;
            mx = fmaxf(mx, fmaxf(m0x, m1x));
            my = fmaxf(my, fmaxf(m0y, m1y));
            lmin = fminf(lmin, fminf(fminf(m0x, m0y), fminf(m1x, m1y)));
        }
        if (e < end) {
            int ei0 = d_ei[e];
            float2 es0 = *(const float2*)&g_esum[ei0 * 64 + 2 * lane];
            float2 em0 = *(const float2*)&g_emax[ei0 * 64 + 2 * lane];
            float sx0 = bs.x + es0.x, sy0 = bs.y + es0.y;
            asx += sx0; asy += sy0;
            aqx += sx0 * sx0; aqy += sy0 * sy0;
            float m0x = bm.x + em0.x, m0y = bm.y + em0.y;
            mx = fmaxf(mx, m0x);
            my = fmaxf(my, m0y);
            lmin = fminf(lmin, fminf(m0x, m0y));
        }
        float2 o; o.x = mx; o.y = my;
        *(float2*)&g_segmax[n * 64 + 2 * lane] = o;
    }

    atomicAdd(&s_acc[2 * lane], asx);
    atomicAdd(&s_acc[2 * lane + 1], asy);
    atomicAdd(&s_acc[64 + 2 * lane], aqx);
    atomicAdd(&s_acc[64 + 2 * lane + 1], aqy);
    #pragma unroll
    for (int off = 16; off; off >>= 1)
        lmin = fminf(lmin, __shfl_xor_sync(0xffffffffu, lmin, off));
    if (lane == 0) atomicMin(&s_min, fkey(lmin));
    __syncthreads();
    if (tid < 64) {
        atomicAdd(&d_sum_s[tid], s_acc[tid]);
        atomicAdd(&d_ss_s[tid], s_acc[64 + tid]);
    }
    if (tid == 0) atomicMin(&d_min_i, s_min);
}

// ---- pass B: relu(bn(ef_sum)) per-node sum + node-BN stats (sumagg half) ----
// edge-BN stats finalized inline from raw sums
__global__ void k_edgeB(const float* __restrict__ gamma,
                        const float* __restrict__ beta) {
    __shared__ float s_acc[128];
    int tid = threadIdx.x;
    int lane = tid & 31;
    if (tid < 128) s_acc[tid] = 0.0f;
    __syncthreads();

    int f0 = 2 * lane, f1 = 2 * lane + 1;
    float mux = d_sum_s[f0] / (float)NE;
    float muy = d_sum_s[f1] / (float)NE;
    float isx = rsqrtf(d_ss_s[f0] / (float)NE - mux * mux + 1e-5f);
    float isy = rsqrtf(d_ss_s[f1] / (float)NE - muy * muy + 1e-5f);
    float ax = isx * gamma[f0], ay = isy * gamma[f1];
    float cx = beta[f0] - mux * ax, cy = beta[f1] - muy * ay;

    int warp = (blockIdx.x * blockDim.x + tid) >> 5;
    int nwarp = (gridDim.x * blockDim.x) >> 5;
    float nsx = 0.f, nsy = 0.f, nqx = 0.f, nqy = 0.f;

    for (int n = warp; n < NN; n += nwarp) {
        int beg = d_row[n], end = d_row[n + 1];
        float2 bs = *(const float2*)&g_bsum[n * 64 + f0];
        float accx = 0.f, accy = 0.f;
        int e = beg;
        for (; e + 1 < end; e += 2) {
            int ei0 = d_ei[e], ei1 = d_ei[e + 1];
            float2 es0 = *(const float2*)&g_esum[ei0 * 64 + f0];
            float2 es1 = *(const float2*)&g_esum[ei1 * 64 + f0];
            accx += fmaxf(0.f, fmaf(bs.x + es0.x, ax, cx))
                  + fmaxf(0.f, fmaf(bs.x + es1.x, ax, cx));
            accy += fmaxf(0.f, fmaf(bs.y + es0.y, ay, cy))
                  + fmaxf(0.f, fmaf(bs.y + es1.y, ay, cy));
        }
        if (e < end) {
            int ei0 = d_ei[e];
            float2 es0 = *(const float2*)&g_esum[ei0 * 64 + f0];
            accx += fmaxf(0.f, fmaf(bs.x + es0.x, ax, cx));
            accy += fmaxf(0.f, fmaf(bs.y + es0.y, ay, cy));
        }
        float2 o; o.x = accx; o.y = accy;
        *(float2*)&g_sumagg[n * 64 + f0] = o;
        nsx += accx; nsy += accy;
        nqx += accx * accx; nqy += accy * accy;
    }

    atomicAdd(&s_acc[f0], nsx);
    atomicAdd(&s_acc[f1], nsy);
    atomicAdd(&s_acc[64 + f0], nqx);
    atomicAdd(&s_acc[64 + f1], nqy);
    __syncthreads();
    if (tid < 64) {
        atomicAdd(&d_sum_g[64 + tid], s_acc[tid]);
        atomicAdd(&d_ss_g[64 + tid], s_acc[64 + tid]);
    }
}

// ---- K5: empty-segment fix + node-BN stats for segmax half ----
__global__ void k_node() {
    __shared__ float s_acc[128];
    int tid = threadIdx.x;
    int lane = tid & 31;
    if (tid < 128) s_acc[tid] = 0.0f;
    __syncthreads();

    int f0 = 2 * lane;
    float minv = fdec(d_min_i);
    int warp = (blockIdx.x * blockDim.x + tid) >> 5;
    int nwarp = (gridDim.x * blockDim.x) >> 5;
    float nsx = 0.f, nsy = 0.f, nqx = 0.f, nqy = 0.f;
    for (int n = warp; n < NN; n += nwarp) {
        float2 v = *(const float2*)&g_segmax[n * 64 + f0];
        if (v.x == -INFINITY) {
            v.x = minv; v.y = minv;
            *(float2*)&g_segmax[n * 64 + f0] = v;
        }
        nsx += v.x; nsy += v.y;
        nqx += v.x * v.x; nqy += v.y * v.y;
    }
    atomicAdd(&s_acc[f0], nsx);
    atomicAdd(&s_acc[f0 + 1], nsy);
    atomicAdd(&s_acc[64 + f0], nqx);
    atomicAdd(&s_acc[64 + f0 + 1], nqy);
    __syncthreads();
    if (tid < 64) {
        atomicAdd(&d_sum_g[tid], s_acc[tid]);
        atomicAdd(&d_ss_g[tid], s_acc[64 + tid]);
    }
}

// ---- K6: finalize node-BN; pack BN-folded W_u into fragment order + doff ----
__global__ void k_fin_g(const float* __restrict__ gamma_u,
                        const float* __restrict__ beta_u,
                        const float* __restrict__ W_u) {
    int t = threadIdx.x;  // 256
    if (t < 128) {
        float mu = d_sum_g[t] / (float)NN;
        float var = d_ss_g[t] / (float)NN - mu * mu;
        float a = rsqrtf(var + 1e-5f) * gamma_u[t];
        d_a_g[t] = a;
        d_c_g[t] = beta_u[t] - mu * a;
    }
    __syncthreads();
    for (int e = t; e < 8 * 2 * 8 * 32; e += 256) {
        int lane = e & 31;
        int t2 = e >> 5;
        int nbk = t2 & 7;
        int ks = (t2 >> 3) & 1;
        int kc = t2 >> 4;
        int g = lane >> 2, tig = lane & 3;
        int k = kc * 16 + ks * 8 + tig;
        int n = nbk * 8 + g;
        float2 v;
        v.x = to_tf32(d_a_g[k] * W_u[k * 64 + n]);
        v.y = to_tf32(d_a_g[k + 4] * W_u[(k + 4) * 64 + n]);
        *(float2*)&d_W2[e * 2] = v;
    }
    if (t < 64) {
        float acc = 0.f;
        for (int k = 0; k < 128; k++) acc += d_c_g[k] * W_u[k * 64 + t];
        d_doff[t] = acc;
    }
}

// ---- K7: GEMM2 tf32 mma: out = self + relu([segmax|sumagg] @ W' + doff) ----
__global__ void __launch_bounds__(256, 2)
k_final(float* __restrict__ out) {
    __shared__ __align__(16) float As[2][256][20];
    int tid = threadIdx.x;
    int lane = tid & 31, wid = tid >> 5;
    int wm = wid & 3, wn = wid >> 2;
    int g = lane >> 2, tig = lane & 3;
    int m0 = blockIdx.x * 256;

    float c[4][4][4];
    #pragma unroll
    for (int mt = 0; mt < 4; mt++)
        #pragma unroll
        for (int nt = 0; nt < 4; nt++)
            #pragma unroll
            for (int i = 0; i < 4; i++) c[mt][nt][i] = 0.0f;

    int frow = tid >> 2;
    int fc = (tid & 3) * 4;

    #pragma unroll
    for (int p = 0; p < 4; p++) {
        int gm = m0 + p * 64 + frow;
        float4 v = make_float4(0.f, 0.f, 0.f, 0.f);
        if (gm < NN) v = *(const float4*)&g_segmax[gm * 64 + fc];
        *(float4*)&As[0][p * 64 + frow][fc] = to_tf32_4(v);
    }
    __syncthreads();

    #pragma unroll
    for (int kci = 0; kci < 8; kci++) {
        int cur = kci & 1;
        float4 pf[4];
        if (kci < 7) {
            int kg = (kci + 1) * 16 + fc;
            const float* src = (kg < 64) ? g_segmax : g_sumagg;
            int off = (kg < 64) ? kg : (kg - 64);
            #pragma unroll
            for (int p = 0; p < 4; p++) {
                int gm = m0 + p * 64 + frow;
                pf[p] = make_float4(0.f, 0.f, 0.f, 0.f);
                if (gm < NN) pf[p] = *(const float4*)&src[gm * 64 + off];
            }
        }

        #pragma unroll
        for (int ks = 0; ks < 2; ks++) {
            int kk = ks * 8 + tig;
            unsigned af[4][4];
            #pragma unroll
            for (int mt = 0; mt < 4; mt++) {
                int mr = wm * 64 + mt * 16;
                af[mt][0] = __float_as_uint(As[cur][mr + g][kk]);
                af[mt][1] = __float_as_uint(As[cur][mr + g + 8][kk]);
                af[mt][2] = __float_as_uint(As[cur][mr + g][kk + 4]);
                af[mt][3] = __float_as_uint(As[cur][mr + g + 8][kk + 4]);
            }
            #pragma unroll
            for (int nt = 0; nt < 4; nt++) {
                int nbk = wn * 4 + nt;
                float2 bf = *(const float2*)&d_W2[(((kci * 2) + ks) * 8 + nbk) * 64 + lane * 2];
                unsigned b0 = __float_as_uint(bf.x);
                unsigned b1 = __float_as_uint(bf.y);
                #pragma unroll
                for (int mt = 0; mt < 4; mt++) {
                    asm volatile(
                        "mma.sync.aligned.m16n8k8.row.col.f32.tf32.tf32.f32 "
                        "{%0,%1,%2,%3}, {%4,%5,%6,%7}, {%8,%9}, {%0,%1,%2,%3};"
                        : "+f"(c[mt][nt][0]), "+f"(c[mt][nt][1]),
                          "+f"(c[mt][nt][2]), "+f"(c[mt][nt][3])
                        : "r"(af[mt][0]), "r"(af[mt][1]), "r"(af[mt][2]), "r"(af[mt][3]),
                          "r"(b0), "r"(b1));
                }
            }
        }

        if (kci < 7) {
            #pragma unroll
            for (int p = 0; p < 4; p++)
                *(float4*)&As[cur ^ 1][p * 64 + frow][fc] = to_tf32_4(pf[p]);
        }
        __syncthreads();
    }

    #pragma unroll
    for (int mt = 0; mt < 4; mt++) {
        #pragma unroll
        for (int nt = 0; nt < 4; nt++) {
            int col = wn * 32 + nt * 8 + tig * 2;
            float dx = d_doff[col], dy = d_doff[col + 1];
            int r0 = m0 + wm * 64 + mt * 16 + g;
            if (r0 < NN) {
                float2 sf = *(const float2*)&g_self[r0 * 64 + col];
                float2 o;
                o.x = sf.x + fmaxf(0.f, c[mt][nt][0] + dx);
                o.y = sf.y + fmaxf(0.f, c[mt][nt][1] + dy);
                *(float2*)&out[r0 * 64 + col] = o;
            }
            int r1 = r0 + 8;
            if (r1 < NN) {
                float2 sf = *(const float2*)&g_self[r1 * 64 + col];
                float2 o;
                o.x = sf.x + fmaxf(0.f, c[mt][nt][2] + dx);
                o.y = sf.y + fmaxf(0.f, c[mt][nt][3] + dy);
                *(float2*)&out[r1 * 64 + col] = o;
            }
        }
    }
}

extern "C" void kernel_launch(void* const* d_in, const int* in_sizes, int n_in,
                              void* d_out, int out_size) {
    const float* n_feat  = (const float*)d_in[0];
    const int*   eidx    = (const int*)d_in[1];
    const float* W_b     = (const float*)d_in[2];
    const float* b_b     = (const float*)d_in[3];
    const float* gamma_g = (const float*)d_in[4];
    const float* beta_g  = (const float*)d_in[5];
    const float* gamma_u = (const float*)d_in[6];
    const float* beta_u  = (const float*)d_in[7];
    const float* W_u     = (const float*)d_in[8];
    float* out           = (float*)d_out;

    const int* begin_ids = eidx;
    const int* end_ids   = eidx + NE;

    static cudaStream_t s1 = 0;
    static cudaEvent_t evFork = 0, evJoin = 0, evFork2 = 0, evJoin2 = 0;
    if (!s1) {
        cudaStreamCreateWithFlags(&s1, cudaStreamNonBlocking);
        cudaEventCreateWithFlags(&evFork, cudaEventDisableTiming);
        cudaEventCreateWithFlags(&evJoin, cudaEventDisableTiming);
        cudaEventCreateWithFlags(&evFork2, cudaEventDisableTiming);
        cudaEventCreateWithFlags(&evJoin2, cudaEventDisableTiming);
    }

    // fork: GEMM chain on s1, CSR chain on default stream — independent
    cudaEventRecord(evFork, 0);
    cudaStreamWaitEvent(s1, evFork, 0);
    k_prepB<<<160, 256, 0, s1>>>(W_b);
    dim3 g1((NN + 255) / 256, 5);
    k_gemm1<<<g1, 256, 0, s1>>>(n_feat, b_b);

    k_init<<<256, 256>>>();
    k_deg<<<1184, 256>>>(begin_ids);
    k_scan1<<<NBLK, SCAN_B>>>();
    k_scan2<<<1, 128>>>();
    k_scan3<<<NBLK, SCAN_B>>>();
    k_fill<<<1184, 256>>>(begin_ids, end_ids);

    // join: edgeA needs GEMM outputs and CSR
    cudaEventRecord(evJoin, s1);
    cudaStreamWaitEvent(0, evJoin, 0);
    k_edgeA<<<1184, 256>>>();

    // fork 2: k_node (needs only edgeA) overlaps edgeB (disjoint d_sum_g halves)
    cudaEventRecord(evFork2, 0);
    cudaStreamWaitEvent(s1, evFork2, 0);
    k_node<<<1184, 256, 0, s1>>>();

    k_edgeB<<<1184, 256>>>(gamma_g, beta_g);

    cudaEventRecord(evJoin2, s1);
    cudaStreamWaitEvent(0, evJoin2, 0);
    k_fin_g<<<1, 256>>>(gamma_u, beta_u, W_u);
    k_final<<<(NN + 255) / 256, 256>>>(out);
}

// round 14
// speedup vs baseline: 1.0804x; 1.0372x over previous
#include <cuda_runtime.h>
#include <math.h>

#define NN 50000
#define NE 800000
#define KIN 128
#define F 64
#define NF (NN*F)
#define SCAN_B 512
#define NBLK ((NN + SCAN_B - 1) / SCAN_B)   // 98

// ---- scratch (device globals; no allocation allowed) ----
__device__ __align__(16) float g_self[NF];
__device__ __align__(16) float g_bsum[NF];
__device__ __align__(16) float g_esum[NF];
__device__ __align__(16) float g_bmax[NF];
__device__ __align__(16) float g_emax[NF];
__device__ __align__(16) float g_segmax[NF];
__device__ __align__(16) float g_sumagg[NF];

__device__ int d_deg[NN];
__device__ int d_row[NN + 1];
__device__ int d_cur[NN];
__device__ int d_bsumI[NBLK];
__device__ int d_ei[NE];          // end ids sorted by begin id

// B (W_b) pre-packed in MMA fragment lane order, tf32-converted.
__device__ __align__(16) float d_B2[5 * 8 * 2 * 8 * 32 * 2];
// BN-folded W_u pre-packed in fragment lane order.
__device__ __align__(16) float d_W2[8 * 2 * 8 * 32 * 2];

__device__ __align__(16) float d_sum_s[64];
__device__ __align__(16) float d_ss_s[64];
__device__ __align__(16) float d_sum_g[128];
__device__ __align__(16) float d_ss_g[128];
__device__ __align__(16) float d_a_g[128];
__device__ __align__(16) float d_c_g[128];
__device__ __align__(16) float d_doff[64];
__device__ int   d_min_i;

// ---- monotone float<->int key ----
__device__ __forceinline__ int fkey(float f) {
    int i = __float_as_int(f);
    return i >= 0 ? i : (i ^ 0x7fffffff);
}
__device__ __forceinline__ float fdec(int k) {
    return __int_as_float(k >= 0 ? k : (k ^ 0x7fffffff));
}

// tf32 cvt: PTX requires .b32 destination register
__device__ __forceinline__ float to_tf32(float v) {
    unsigned r;
    asm("cvt.rna.tf32.f32 %0, %1;" : "=r"(r) : "f"(v));
    return __uint_as_float(r);
}
__device__ __forceinline__ float4 to_tf32_4(float4 v) {
    float4 r;
    r.x = to_tf32(v.x); r.y = to_tf32(v.y);
    r.z = to_tf32(v.z); r.w = to_tf32(v.w);
    return r;
}

// ---- K0: init small scratch ----
__global__ void k_init() {
    int i = blockIdx.x * blockDim.x + threadIdx.x;
    int stride = gridDim.x * blockDim.x;
    for (int j = i; j < NN; j += stride) d_deg[j] = 0;
    if (i < 64)  { d_sum_s[i] = 0.0f; d_ss_s[i] = 0.0f; }
    if (i < 128) { d_sum_g[i] = 0.0f; d_ss_g[i] = 0.0f; }
    if (i == 0)  d_min_i = INT_MAX;
}

// ---- CSR build ----
__global__ void k_deg(const int* __restrict__ b) {
    int i = blockIdx.x * blockDim.x + threadIdx.x;
    int stride = gridDim.x * blockDim.x;
    for (; i < NE; i += stride) atomicAdd(&d_deg[b[i]], 1);
}

// ---- pre-pack B into fragment lane order (tf32) ----
__global__ void k_prepB(const float* __restrict__ B) {  // [128,320]
    int idx = blockIdx.x * blockDim.x + threadIdx.x;    // 0..40959
    if (idx >= 5 * 8 * 2 * 8 * 32) return;
    int lane = idx & 31;
    int t = idx >> 5;
    int nbk = t & 7;  t >>= 3;
    int ks  = t & 1;  t >>= 1;
    int kc  = t & 7;  t >>= 3;
    int slice = t;                      // 0..4
    int g = lane >> 2, tig = lane & 3;
    int k = kc * 16 + ks * 8 + tig;
    int n = slice * 64 + nbk * 8 + g;
    float2 v;
    v.x = to_tf32(B[k * 320 + n]);
    v.y = to_tf32(B[(k + 4) * 320 + n]);
    *(float2*)&d_B2[idx * 2] = v;
}

__global__ void k_scan1() {
    __shared__ int sh[SCAN_B];
    int i = blockIdx.x * SCAN_B + threadIdx.x;
    sh[threadIdx.x] = (i < NN) ? d_deg[i] : 0;
    __syncthreads();
    for (int off = SCAN_B / 2; off; off >>= 1) {
        if (threadIdx.x < off) sh[threadIdx.x] += sh[threadIdx.x + off];
        __syncthreads();
    }
    if (threadIdx.x == 0) d_bsumI[blockIdx.x] = sh[0];
}

// scan3 with inlined block-offset computation (scan2 folded in)
__global__ void k_scan3() {
    int t = threadIdx.x;
    int lane = t & 31, w = t >> 5;
    __shared__ int sOff;
    // warp 0 computes exclusive prefix of block sums for this block
    if (w == 0) {
        int acc = 0;
        for (int j = lane; j < blockIdx.x; j += 32) acc += d_bsumI[j];
        #pragma unroll
        for (int off = 16; off; off >>= 1)
            acc += __shfl_xor_sync(0xffffffffu, acc, off);
        if (lane == 0) sOff = acc;
    }
    int i = blockIdx.x * SCAN_B + t;
    int v = (i < NN) ? d_deg[i] : 0;
    int x = v;
    #pragma unroll
    for (int off = 1; off < 32; off <<= 1) {
        int y = __shfl_up_sync(0xffffffffu, x, off);
        if (lane >= off) x += y;
    }
    __shared__ int wt[16];
    if (lane == 31) wt[w] = x;
    __syncthreads();
    int add = sOff;
    for (int k = 0; k < w; k++) add += wt[k];
    int excl = x - v + add;
    if (i < NN) { d_row[i] = excl; d_cur[i] = excl; }
    if (blockIdx.x == 0 && t == 0) d_row[NN] = NE;
}

__global__ void k_fill(const int* __restrict__ b, const int* __restrict__ e) {
    int i = blockIdx.x * blockDim.x + threadIdx.x;
    int stride = gridDim.x * blockDim.x;
    for (; i < NE; i += stride) {
        int pos = atomicAdd(&d_cur[b[i]], 1);
        d_ei[pos] = e[i];
    }
}

// ---- K1: GEMM1 tf32 mma.sync; A double-buffered + B slice cached in smem ----
// dynamic smem: [0,10240) As (2 bufs x 256 x 20), [10240,18432) Bs (8192)
__global__ void __launch_bounds__(256, 2)
k_gemm1(const float* __restrict__ A,    // [NN,128]
        const float* __restrict__ bias) // [320]
{
    extern __shared__ __align__(16) float sm[];
    float* AsB = sm;
    float* Bs  = sm + 10240;
    #define AS_(c, r, k) AsB[(c) * 5120 + (r) * 20 + (k)]

    int tid = threadIdx.x;
    int lane = tid & 31, wid = tid >> 5;
    int wm = wid & 3, wn = wid >> 2;
    int g = lane >> 2, tig = lane & 3;
    int m0 = blockIdx.x * 256;
    int nb = blockIdx.y;

    float c[4][4][4];
    #pragma unroll
    for (int mt = 0; mt < 4; mt++)
        #pragma unroll
        for (int nt = 0; nt < 4; nt++)
            #pragma unroll
            for (int i = 0; i < 4; i++) c[mt][nt][i] = 0.0f;

    int frow = tid >> 2;
    int fc = (tid & 3) * 4;

    // cooperative copy of this slice's packed B (8192 floats = 2048 float4)
    {
        const float4* src = (const float4*)&d_B2[nb * 8192];
        float4* dst = (float4*)Bs;
        #pragma unroll
        for (int i = 0; i < 8; i++) dst[tid + i * 256] = src[tid + i * 256];
    }

    #pragma unroll
    for (int p = 0; p < 4; p++) {
        int row = p * 64 + frow;
        int gm = m0 + row;
        float4 v = make_float4(0.f, 0.f, 0.f, 0.f);
        if (gm < NN) v = *(const float4*)&A[gm * KIN + fc];
        *(float4*)&AS_(0, row, fc) = to_tf32_4(v);
    }
    __syncthreads();

    #pragma unroll
    for (int kci = 0; kci < 8; kci++) {
        int cur = kci & 1;
        float4 pf[4];
        if (kci < 7) {
            int kc = (kci + 1) * 16;
            #pragma unroll
            for (int p = 0; p < 4; p++) {
                int gm = m0 + p * 64 + frow;
                pf[p] = make_float4(0.f, 0.f, 0.f, 0.f);
                if (gm < NN) pf[p] = *(const float4*)&A[gm * KIN + kc + fc];
            }
        }

        #pragma unroll
        for (int ks = 0; ks < 2; ks++) {
            int kk = ks * 8 + tig;
            unsigned af[4][4];
            #pragma unroll
            for (int mt = 0; mt < 4; mt++) {
                int mr = wm * 64 + mt * 16;
                af[mt][0] = __float_as_uint(AS_(cur, mr + g, kk));
                af[mt][1] = __float_as_uint(AS_(cur, mr + g + 8, kk));
                af[mt][2] = __float_as_uint(AS_(cur, mr + g, kk + 4));
                af[mt][3] = __float_as_uint(AS_(cur, mr + g + 8, kk + 4));
            }
            #pragma unroll
            for (int nt = 0; nt < 4; nt++) {
                int nbk = wn * 4 + nt;
                float2 bf = *(const float2*)&Bs[(((kci * 2) + ks) * 8 + nbk) * 64 + lane * 2];
                unsigned b0 = __float_as_uint(bf.x);
                unsigned b1 = __float_as_uint(bf.y);
                #pragma unroll
                for (int mt = 0; mt < 4; mt++) {
                    asm volatile(
                        "mma.sync.aligned.m16n8k8.row.col.f32.tf32.tf32.f32 "
                        "{%0,%1,%2,%3}, {%4,%5,%6,%7}, {%8,%9}, {%0,%1,%2,%3};"
                        : "+f"(c[mt][nt][0]), "+f"(c[mt][nt][1]),
                          "+f"(c[mt][nt][2]), "+f"(c[mt][nt][3])
                        : "r"(af[mt][0]), "r"(af[mt][1]), "r"(af[mt][2]), "r"(af[mt][3]),
                          "r"(b0), "r"(b1));
                }
            }
        }

        if (kci < 7) {
            #pragma unroll
            for (int p = 0; p < 4; p++)
                *(float4*)&AS_(cur ^ 1, p * 64 + frow, fc) = to_tf32_4(pf[p]);
        }
        __syncthreads();
    }

    int n0 = nb * 64;
    float* outp = (nb == 0) ? g_self : (nb == 1) ? g_bsum :
                  (nb == 2) ? g_esum : (nb == 3) ? g_bmax : g_emax;
    #pragma unroll
    for (int mt = 0; mt < 4; mt++) {
        #pragma unroll
        for (int nt = 0; nt < 4; nt++) {
            int col = wn * 32 + nt * 8 + tig * 2;
            float bx = bias[n0 + col], by = bias[n0 + col + 1];
            int r0 = m0 + wm * 64 + mt * 16 + g;
            if (r0 < NN) {
                float2 o; o.x = c[mt][nt][0] + bx; o.y = c[mt][nt][1] + by;
                *(float2*)&outp[r0 * 64 + col] = o;
            }
            int r1 = r0 + 8;
            if (r1 < NN) {
                float2 o; o.x = c[mt][nt][2] + bx; o.y = c[mt][nt][3] + by;
                *(float2*)&outp[r1 * 64 + col] = o;
            }
        }
    }
    #undef AS_
}

// ---- pass A: per-node segment max + edge-BN stats + global min (2-edge unroll) ----
__global__ void k_edgeA() {
    __shared__ float s_acc[128];
    __shared__ int s_min;
    int tid = threadIdx.x;
    int lane = tid & 31;
    if (tid < 128) s_acc[tid] = 0.0f;
    if (tid == 0) s_min = INT_MAX;
    __syncthreads();

    int warp = (blockIdx.x * blockDim.x + tid) >> 5;
    int nwarp = (gridDim.x * blockDim.x) >> 5;
    float asx = 0.f, asy = 0.f, aqx = 0.f, aqy = 0.f;
    float lmin = INFINITY;

    for (int n = warp; n < NN; n += nwarp) {
        int beg = d_row[n], end = d_row[n + 1];
        float2 bs = *(const float2*)&g_bsum[n * 64 + 2 * lane];
        float2 bm = *(const float2*)&g_bmax[n * 64 + 2 * lane];
        float mx = -INFINITY, my = -INFINITY;
        int e = beg;
        for (; e + 1 < end; e += 2) {
            int ei0 = d_ei[e], ei1 = d_ei[e + 1];
            float2 es0 = *(const float2*)&g_esum[ei0 * 64 + 2 * lane];
            float2 em0 = *(const float2*)&g_emax[ei0 * 64 + 2 * lane];
            float2 es1 = *(const float2*)&g_esum[ei1 * 64 + 2 * lane];
            float2 em1 = *(const float2*)&g_emax[ei1 * 64 + 2 * lane];
            float sx0 = bs.x + es0.x, sy0 = bs.y + es0.y;
            float sx1 = bs.x + es1.x, sy1 = bs.y + es1.y;
            asx += sx0 + sx1; asy += sy0 + sy1;
            aqx += sx0 * sx0 + sx1 * sx1;
            aqy += sy0 * sy0 + sy1 * sy1;
            float m0x = bm.x + em0.x, m0y = bm.y + em0.y;
            float m1x = bm.x + em1.x, m1y = bm.y + em1.y;
            mx = fmaxf(mx, fmaxf(m0x, m1x));
            my = fmaxf(my, fmaxf(m0y, m1y));
            lmin = fminf(lmin, fminf(fminf(m0x, m0y), fminf(m1x, m1y)));
        }
        if (e < end) {
            int ei0 = d_ei[e];
            float2 es0 = *(const float2*)&g_esum[ei0 * 64 + 2 * lane];
            float2 em0 = *(const float2*)&g_emax[ei0 * 64 + 2 * lane];
            float sx0 = bs.x + es0.x, sy0 = bs.y + es0.y;
            asx += sx0; asy += sy0;
            aqx += sx0 * sx0; aqy += sy0 * sy0;
            float m0x = bm.x + em0.x, m0y = bm.y + em0.y;
            mx = fmaxf(mx, m0x);
            my = fmaxf(my, m0y);
            lmin = fminf(lmin, fminf(m0x, m0y));
        }
        float2 o; o.x = mx; o.y = my;
        *(float2*)&g_segmax[n * 64 + 2 * lane] = o;
    }

    atomicAdd(&s_acc[2 * lane], asx);
    atomicAdd(&s_acc[2 * lane + 1], asy);
    atomicAdd(&s_acc[64 + 2 * lane], aqx);
    atomicAdd(&s_acc[64 + 2 * lane + 1], aqy);
    #pragma unroll
    for (int off = 16; off; off >>= 1)
        lmin = fminf(lmin, __shfl_xor_sync(0xffffffffu, lmin, off));
    if (lane == 0) atomicMin(&s_min, fkey(lmin));
    __syncthreads();
    if (tid < 64) {
        atomicAdd(&d_sum_s[tid], s_acc[tid]);
        atomicAdd(&d_ss_s[tid], s_acc[64 + tid]);
    }
    if (tid == 0) atomicMin(&d_min_i, s_min);
}

// ---- pass B: relu(bn(ef_sum)) per-node sum + node-BN stats (sumagg half) ----
__global__ void k_edgeB(const float* __restrict__ gamma,
                        const float* __restrict__ beta) {
    __shared__ float s_acc[128];
    int tid = threadIdx.x;
    int lane = tid & 31;
    if (tid < 128) s_acc[tid] = 0.0f;
    __syncthreads();

    int f0 = 2 * lane, f1 = 2 * lane + 1;
    float mux = d_sum_s[f0] / (float)NE;
    float muy = d_sum_s[f1] / (float)NE;
    float isx = rsqrtf(d_ss_s[f0] / (float)NE - mux * mux + 1e-5f);
    float isy = rsqrtf(d_ss_s[f1] / (float)NE - muy * muy + 1e-5f);
    float ax = isx * gamma[f0], ay = isy * gamma[f1];
    float cx = beta[f0] - mux * ax, cy = beta[f1] - muy * ay;

    int warp = (blockIdx.x * blockDim.x + tid) >> 5;
    int nwarp = (gridDim.x * blockDim.x) >> 5;
    float nsx = 0.f, nsy = 0.f, nqx = 0.f, nqy = 0.f;

    for (int n = warp; n < NN; n += nwarp) {
        int beg = d_row[n], end = d_row[n + 1];
        float2 bs = *(const float2*)&g_bsum[n * 64 + f0];
        float accx = 0.f, accy = 0.f;
        int e = beg;
        for (; e + 1 < end; e += 2) {
            int ei0 = d_ei[e], ei1 = d_ei[e + 1];
            float2 es0 = *(const float2*)&g_esum[ei0 * 64 + f0];
            float2 es1 = *(const float2*)&g_esum[ei1 * 64 + f0];
            accx += fmaxf(0.f, fmaf(bs.x + es0.x, ax, cx))
                  + fmaxf(0.f, fmaf(bs.x + es1.x, ax, cx));
            accy += fmaxf(0.f, fmaf(bs.y + es0.y, ay, cy))
                  + fmaxf(0.f, fmaf(bs.y + es1.y, ay, cy));
        }
        if (e < end) {
            int ei0 = d_ei[e];
            float2 es0 = *(const float2*)&g_esum[ei0 * 64 + f0];
            accx += fmaxf(0.f, fmaf(bs.x + es0.x, ax, cx));
            accy += fmaxf(0.f, fmaf(bs.y + es0.y, ay, cy));
        }
        float2 o; o.x = accx; o.y = accy;
        *(float2*)&g_sumagg[n * 64 + f0] = o;
        nsx += accx; nsy += accy;
        nqx += accx * accx; nqy += accy * accy;
    }

    atomicAdd(&s_acc[f0], nsx);
    atomicAdd(&s_acc[f1], nsy);
    atomicAdd(&s_acc[64 + f0], nqx);
    atomicAdd(&s_acc[64 + f1], nqy);
    __syncthreads();
    if (tid < 64) {
        atomicAdd(&d_sum_g[64 + tid], s_acc[tid]);
        atomicAdd(&d_ss_g[64 + tid], s_acc[64 + tid]);
    }
}

// ---- K5: empty-segment fix + node-BN stats for segmax half ----
__global__ void k_node() {
    __shared__ float s_acc[128];
    int tid = threadIdx.x;
    int lane = tid & 31;
    if (tid < 128) s_acc[tid] = 0.0f;
    __syncthreads();

    int f0 = 2 * lane;
    float minv = fdec(d_min_i);
    int warp = (blockIdx.x * blockDim.x + tid) >> 5;
    int nwarp = (gridDim.x * blockDim.x) >> 5;
    float nsx = 0.f, nsy = 0.f, nqx = 0.f, nqy = 0.f;
    for (int n = warp; n < NN; n += nwarp) {
        float2 v = *(const float2*)&g_segmax[n * 64 + f0];
        if (v.x == -INFINITY) {
            v.x = minv; v.y = minv;
            *(float2*)&g_segmax[n * 64 + f0] = v;
        }
        nsx += v.x; nsy += v.y;
        nqx += v.x * v.x; nqy += v.y * v.y;
    }
    atomicAdd(&s_acc[f0], nsx);
    atomicAdd(&s_acc[f0 + 1], nsy);
    atomicAdd(&s_acc[64 + f0], nqx);
    atomicAdd(&s_acc[64 + f0 + 1], nqy);
    __syncthreads();
    if (tid < 64) {
        atomicAdd(&d_sum_g[tid], s_acc[tid]);
        atomicAdd(&d_ss_g[tid], s_acc[64 + tid]);
    }
}

// ---- K6: finalize node-BN; pack BN-folded W_u into fragment order + doff ----
__global__ void k_fin_g(const float* __restrict__ gamma_u,
                        const float* __restrict__ beta_u,
                        const float* __restrict__ W_u) {
    int t = threadIdx.x;  // 256
    if (t < 128) {
        float mu = d_sum_g[t] / (float)NN;
        float var = d_ss_g[t] / (float)NN - mu * mu;
        float a = rsqrtf(var + 1e-5f) * gamma_u[t];
        d_a_g[t] = a;
        d_c_g[t] = beta_u[t] - mu * a;
    }
    __syncthreads();
    for (int e = t; e < 8 * 2 * 8 * 32; e += 256) {
        int lane = e & 31;
        int t2 = e >> 5;
        int nbk = t2 & 7;
        int ks = (t2 >> 3) & 1;
        int kc = t2 >> 4;
        int g = lane >> 2, tig = lane & 3;
        int k = kc * 16 + ks * 8 + tig;
        int n = nbk * 8 + g;
        float2 v;
        v.x = to_tf32(d_a_g[k] * W_u[k * 64 + n]);
        v.y = to_tf32(d_a_g[k + 4] * W_u[(k + 4) * 64 + n]);
        *(float2*)&d_W2[e * 2] = v;
    }
    if (t < 64) {
        float acc = 0.f;
        for (int k = 0; k < 128; k++) acc += d_c_g[k] * W_u[k * 64 + t];
        d_doff[t] = acc;
    }
}

// ---- K7: GEMM2 tf32 mma: out = self + relu([segmax|sumagg] @ W' + doff) ----
__global__ void __launch_bounds__(256, 2)
k_final(float* __restrict__ out) {
    __shared__ __align__(16) float As[2][256][20];
    int tid = threadIdx.x;
    int lane = tid & 31, wid = tid >> 5;
    int wm = wid & 3, wn = wid >> 2;
    int g = lane >> 2, tig = lane & 3;
    int m0 = blockIdx.x * 256;

    float c[4][4][4];
    #pragma unroll
    for (int mt = 0; mt < 4; mt++)
        #pragma unroll
        for (int nt = 0; nt < 4; nt++)
            #pragma unroll
            for (int i = 0; i < 4; i++) c[mt][nt][i] = 0.0f;

    int frow = tid >> 2;
    int fc = (tid & 3) * 4;

    #pragma unroll
    for (int p = 0; p < 4; p++) {
        int gm = m0 + p * 64 + frow;
        float4 v = make_float4(0.f, 0.f, 0.f, 0.f);
        if (gm < NN) v = *(const float4*)&g_segmax[gm * 64 + fc];
        *(float4*)&As[0][p * 64 + frow][fc] = to_tf32_4(v);
    }
    __syncthreads();

    #pragma unroll
    for (int kci = 0; kci < 8; kci++) {
        int cur = kci & 1;
        float4 pf[4];
        if (kci < 7) {
            int kg = (kci + 1) * 16 + fc;
            const float* src = (kg < 64) ? g_segmax : g_sumagg;
            int off = (kg < 64) ? kg : (kg - 64);
            #pragma unroll
            for (int p = 0; p < 4; p++) {
                int gm = m0 + p * 64 + frow;
                pf[p] = make_float4(0.f, 0.f, 0.f, 0.f);
                if (gm < NN) pf[p] = *(const float4*)&src[gm * 64 + off];
            }
        }

        #pragma unroll
        for (int ks = 0; ks < 2; ks++) {
            int kk = ks * 8 + tig;
            unsigned af[4][4];
            #pragma unroll
            for (int mt = 0; mt < 4; mt++) {
                int mr = wm * 64 + mt * 16;
                af[mt][0] = __float_as_uint(As[cur][mr + g][kk]);
                af[mt][1] = __float_as_uint(As[cur][mr + g + 8][kk]);
                af[mt][2] = __float_as_uint(As[cur][mr + g][kk + 4]);
                af[mt][3] = __float_as_uint(As[cur][mr + g + 8][kk + 4]);
            }
            #pragma unroll
            for (int nt = 0; nt < 4; nt++) {
                int nbk = wn * 4 + nt;
                float2 bf = *(const float2*)&d_W2[(((kci * 2) + ks) * 8 + nbk) * 64 + lane * 2];
                unsigned b0 = __float_as_uint(bf.x);
                unsigned b1 = __float_as_uint(bf.y);
                #pragma unroll
                for (int mt = 0; mt < 4; mt++) {
                    asm volatile(
                        "mma.sync.aligned.m16n8k8.row.col.f32.tf32.tf32.f32 "
                        "{%0,%1,%2,%3}, {%4,%5,%6,%7}, {%8,%9}, {%0,%1,%2,%3};"
                        : "+f"(c[mt][nt][0]), "+f"(c[mt][nt][1]),
                          "+f"(c[mt][nt][2]), "+f"(c[mt][nt][3])
                        : "r"(af[mt][0]), "r"(af[mt][1]), "r"(af[mt][2]), "r"(af[mt][3]),
                          "r"(b0), "r"(b1));
                }
            }
        }

        if (kci < 7) {
            #pragma unroll
            for (int p = 0; p < 4; p++)
                *(float4*)&As[cur ^ 1][p * 64 + frow][fc] = to_tf32_4(pf[p]);
        }
        __syncthreads();
    }

    #pragma unroll
    for (int mt = 0; mt < 4; mt++) {
        #pragma unroll
        for (int nt = 0; nt < 4; nt++) {
            int col = wn * 32 + nt * 8 + tig * 2;
            float dx = d_doff[col], dy = d_doff[col + 1];
            int r0 = m0 + wm * 64 + mt * 16 + g;
            if (r0 < NN) {
                float2 sf = *(const float2*)&g_self[r0 * 64 + col];
                float2 o;
                o.x = sf.x + fmaxf(0.f, c[mt][nt][0] + dx);
                o.y = sf.y + fmaxf(0.f, c[mt][nt][1] + dy);
                *(float2*)&out[r0 * 64 + col] = o;
            }
            int r1 = r0 + 8;
            if (r1 < NN) {
                float2 sf = *(const float2*)&g_self[r1 * 64 + col];
                float2 o;
                o.x = sf.x + fmaxf(0.f, c[mt][nt][2] + dx);
                o.y = sf.y + fmaxf(0.f, c[mt][nt][3] + dy);
                *(float2*)&out[r1 * 64 + col] = o;
            }
        }
    }
}

extern "C" void kernel_launch(void* const* d_in, const int* in_sizes, int n_in,
                              void* d_out, int out_size) {
    const float* n_feat  = (const float*)d_in[0];
    const int*   eidx    = (const int*)d_in[1];
    const float* W_b     = (const float*)d_in[2];
    const float* b_b     = (const float*)d_in[3];
    const float* gamma_g = (const float*)d_in[4];
    const float* beta_g  = (const float*)d_in[5];
    const float* gamma_u = (const float*)d_in[6];
    const float* beta_u  = (const float*)d_in[7];
    const float* W_u     = (const float*)d_in[8];
    float* out           = (float*)d_out;

    const int* begin_ids = eidx;
    const int* end_ids   = eidx + NE;

    static cudaStream_t s1 = 0;
    static cudaEvent_t evFork = 0, evJoin = 0, evFork2 = 0, evJoin2 = 0;
    if (!s1) {
        cudaStreamCreateWithFlags(&s1, cudaStreamNonBlocking);
        cudaEventCreateWithFlags(&evFork, cudaEventDisableTiming);
        cudaEventCreateWithFlags(&evJoin, cudaEventDisableTiming);
        cudaEventCreateWithFlags(&evFork2, cudaEventDisableTiming);
        cudaEventCreateWithFlags(&evJoin2, cudaEventDisableTiming);
        cudaFuncSetAttribute(k_gemm1, cudaFuncAttributeMaxDynamicSharedMemorySize, 73728);
    }

    // fork: GEMM chain on s1, CSR chain on default stream — independent
    cudaEventRecord(evFork, 0);
    cudaStreamWaitEvent(s1, evFork, 0);
    k_prepB<<<160, 256, 0, s1>>>(W_b);
    dim3 g1((NN + 255) / 256, 5);
    k_gemm1<<<g1, 256, 73728, s1>>>(n_feat, b_b);

    k_init<<<256, 256>>>();
    k_deg<<<1184, 256>>>(begin_ids);
    k_scan1<<<NBLK, SCAN_B>>>();
    k_scan3<<<NBLK, SCAN_B>>>();
    k_fill<<<1184, 256>>>(begin_ids, end_ids);

    // join: edgeA needs GEMM outputs and CSR
    cudaEventRecord(evJoin, s1);
    cudaStreamWaitEvent(0, evJoin, 0);
    k_edgeA<<<1184, 256>>>();

    // fork 2: k_node (needs only edgeA) overlaps edgeB (disjoint d_sum_g halves)
    cudaEventRecord(evFork2, 0);
    cudaStreamWaitEvent(s1, evFork2, 0);
    k_node<<<1184, 256, 0, s1>>>();

    k_edgeB<<<1184, 256>>>(gamma_g, beta_g);

    cudaEventRecord(evJoin2, s1);
    cudaStreamWaitEvent(0, evJoin2, 0);
    k_fin_g<<<1, 256>>>(gamma_u, beta_u, W_u);
    k_final<<<(NN + 255) / 256, 256>>>(out);
}

// round 15
// speedup vs baseline: 1.0932x; 1.0118x over previous
#include <cuda_runtime.h>
#include <math.h>

#define NN 50000
#define NE 800000
#define KIN 128
#define F 64
#define NF (NN*F)
#define SCAN_B 512
#define NBLK ((NN + SCAN_B - 1) / SCAN_B)   // 98

// ---- scratch (device globals; no allocation allowed) ----
__device__ __align__(16) float g_self[NF];
__device__ __align__(16) float g_bsum[NF];
__device__ __align__(16) float g_esum[NF];
__device__ __align__(16) float g_bmax[NF];
__device__ __align__(16) float g_emax[NF];
__device__ __align__(16) float g_segmax[NF];
__device__ __align__(16) float g_sumagg[NF];

__device__ int d_deg[NN];
__device__ int d_row[NN + 1];
__device__ int d_cur[NN];
__device__ int d_bsumI[NBLK];
__device__ int d_ei[NE];          // end ids sorted by begin id

// B (W_b) pre-packed in MMA fragment lane order, tf32-converted.
__device__ __align__(16) float d_B2[5 * 8 * 2 * 8 * 32 * 2];
// RAW W_u pre-packed in fragment lane order (BN scale applied to A-side).
__device__ __align__(16) float d_W2[8 * 2 * 8 * 32 * 2];

__device__ __align__(16) float d_sum_s[64];
__device__ __align__(16) float d_ss_s[64];
__device__ __align__(16) float d_sum_g[128];
__device__ __align__(16) float d_ss_g[128];
__device__ __align__(16) float d_a_g[128];
__device__ __align__(16) float d_c_g[128];
__device__ __align__(16) float d_doff[64];
__device__ int   d_min_i;

// ---- monotone float<->int key ----
__device__ __forceinline__ int fkey(float f) {
    int i = __float_as_int(f);
    return i >= 0 ? i : (i ^ 0x7fffffff);
}
__device__ __forceinline__ float fdec(int k) {
    return __int_as_float(k >= 0 ? k : (k ^ 0x7fffffff));
}

// tf32 cvt: PTX requires .b32 destination register
__device__ __forceinline__ float to_tf32(float v) {
    unsigned r;
    asm("cvt.rna.tf32.f32 %0, %1;" : "=r"(r) : "f"(v));
    return __uint_as_float(r);
}
__device__ __forceinline__ float4 to_tf32_4(float4 v) {
    float4 r;
    r.x = to_tf32(v.x); r.y = to_tf32(v.y);
    r.z = to_tf32(v.z); r.w = to_tf32(v.w);
    return r;
}

// ---- K0: init small scratch ----
__global__ void k_init() {
    int i = blockIdx.x * blockDim.x + threadIdx.x;
    int stride = gridDim.x * blockDim.x;
    for (int j = i; j < NN; j += stride) d_deg[j] = 0;
    if (i < 64)  { d_sum_s[i] = 0.0f; d_ss_s[i] = 0.0f; }
    if (i < 128) { d_sum_g[i] = 0.0f; d_ss_g[i] = 0.0f; }
    if (i == 0)  d_min_i = INT_MAX;
}

// ---- CSR build ----
__global__ void k_deg(const int* __restrict__ b) {
    int i = blockIdx.x * blockDim.x + threadIdx.x;
    int stride = gridDim.x * blockDim.x;
    for (; i < NE; i += stride) atomicAdd(&d_deg[b[i]], 1);
}

// ---- pre-pack B into fragment lane order (tf32) ----
__global__ void k_prepB(const float* __restrict__ B) {  // [128,320]
    int idx = blockIdx.x * blockDim.x + threadIdx.x;    // 0..40959
    if (idx >= 5 * 8 * 2 * 8 * 32) return;
    int lane = idx & 31;
    int t = idx >> 5;
    int nbk = t & 7;  t >>= 3;
    int ks  = t & 1;  t >>= 1;
    int kc  = t & 7;  t >>= 3;
    int slice = t;                      // 0..4
    int g = lane >> 2, tig = lane & 3;
    int k = kc * 16 + ks * 8 + tig;
    int n = slice * 64 + nbk * 8 + g;
    float2 v;
    v.x = to_tf32(B[k * 320 + n]);
    v.y = to_tf32(B[(k + 4) * 320 + n]);
    *(float2*)&d_B2[idx * 2] = v;
}

// ---- pre-pack RAW W_u into fragment lane order (tf32); no stats needed ----
__global__ void k_prepW(const float* __restrict__ W_u) { // [128,64]
    int idx = blockIdx.x * blockDim.x + threadIdx.x;     // 0..4095
    if (idx >= 8 * 2 * 8 * 32) return;
    int lane = idx & 31;
    int t2 = idx >> 5;
    int nbk = t2 & 7;
    int ks = (t2 >> 3) & 1;
    int kc = t2 >> 4;
    int g = lane >> 2, tig = lane & 3;
    int k = kc * 16 + ks * 8 + tig;
    int n = nbk * 8 + g;
    float2 v;
    v.x = to_tf32(W_u[k * 64 + n]);
    v.y = to_tf32(W_u[(k + 4) * 64 + n]);
    *(float2*)&d_W2[idx * 2] = v;
}

__global__ void k_scan1() {
    __shared__ int sh[SCAN_B];
    int i = blockIdx.x * SCAN_B + threadIdx.x;
    sh[threadIdx.x] = (i < NN) ? d_deg[i] : 0;
    __syncthreads();
    for (int off = SCAN_B / 2; off; off >>= 1) {
        if (threadIdx.x < off) sh[threadIdx.x] += sh[threadIdx.x + off];
        __syncthreads();
    }
    if (threadIdx.x == 0) d_bsumI[blockIdx.x] = sh[0];
}

// scan3 with inlined block-offset computation (scan2 folded in)
__global__ void k_scan3() {
    int t = threadIdx.x;
    int lane = t & 31, w = t >> 5;
    __shared__ int sOff;
    if (w == 0) {
        int acc = 0;
        for (int j = lane; j < blockIdx.x; j += 32) acc += d_bsumI[j];
        #pragma unroll
        for (int off = 16; off; off >>= 1)
            acc += __shfl_xor_sync(0xffffffffu, acc, off);
        if (lane == 0) sOff = acc;
    }
    int i = blockIdx.x * SCAN_B + t;
    int v = (i < NN) ? d_deg[i] : 0;
    int x = v;
    #pragma unroll
    for (int off = 1; off < 32; off <<= 1) {
        int y = __shfl_up_sync(0xffffffffu, x, off);
        if (lane >= off) x += y;
    }
    __shared__ int wt[16];
    if (lane == 31) wt[w] = x;
    __syncthreads();
    int add = sOff;
    for (int k = 0; k < w; k++) add += wt[k];
    int excl = x - v + add;
    if (i < NN) { d_row[i] = excl; d_cur[i] = excl; }
    if (blockIdx.x == 0 && t == 0) d_row[NN] = NE;
}

__global__ void k_fill(const int* __restrict__ b, const int* __restrict__ e) {
    int i = blockIdx.x * blockDim.x + threadIdx.x;
    int stride = gridDim.x * blockDim.x;
    for (; i < NE; i += stride) {
        int pos = atomicAdd(&d_cur[b[i]], 1);
        d_ei[pos] = e[i];
    }
}

// ---- K1: GEMM1 tf32 mma.sync; A double-buffered + B slice cached in smem ----
__global__ void __launch_bounds__(256, 2)
k_gemm1(const float* __restrict__ A,    // [NN,128]
        const float* __restrict__ bias) // [320]
{
    extern __shared__ __align__(16) float sm[];
    float* AsB = sm;
    float* Bs  = sm + 10240;
    #define AS_(c, r, k) AsB[(c) * 5120 + (r) * 20 + (k)]

    int tid = threadIdx.x;
    int lane = tid & 31, wid = tid >> 5;
    int wm = wid & 3, wn = wid >> 2;
    int g = lane >> 2, tig = lane & 3;
    int m0 = blockIdx.x * 256;
    int nb = blockIdx.y;

    float c[4][4][4];
    #pragma unroll
    for (int mt = 0; mt < 4; mt++)
        #pragma unroll
        for (int nt = 0; nt < 4; nt++)
            #pragma unroll
            for (int i = 0; i < 4; i++) c[mt][nt][i] = 0.0f;

    int frow = tid >> 2;
    int fc = (tid & 3) * 4;

    {
        const float4* src = (const float4*)&d_B2[nb * 8192];
        float4* dst = (float4*)Bs;
        #pragma unroll
        for (int i = 0; i < 8; i++) dst[tid + i * 256] = src[tid + i * 256];
    }

    #pragma unroll
    for (int p = 0; p < 4; p++) {
        int row = p * 64 + frow;
        int gm = m0 + row;
        float4 v = make_float4(0.f, 0.f, 0.f, 0.f);
        if (gm < NN) v = *(const float4*)&A[gm * KIN + fc];
        *(float4*)&AS_(0, row, fc) = to_tf32_4(v);
    }
    __syncthreads();

    #pragma unroll
    for (int kci = 0; kci < 8; kci++) {
        int cur = kci & 1;
        float4 pf[4];
        if (kci < 7) {
            int kc = (kci + 1) * 16;
            #pragma unroll
            for (int p = 0; p < 4; p++) {
                int gm = m0 + p * 64 + frow;
                pf[p] = make_float4(0.f, 0.f, 0.f, 0.f);
                if (gm < NN) pf[p] = *(const float4*)&A[gm * KIN + kc + fc];
            }
        }

        #pragma unroll
        for (int ks = 0; ks < 2; ks++) {
            int kk = ks * 8 + tig;
            unsigned af[4][4];
            #pragma unroll
            for (int mt = 0; mt < 4; mt++) {
                int mr = wm * 64 + mt * 16;
                af[mt][0] = __float_as_uint(AS_(cur, mr + g, kk));
                af[mt][1] = __float_as_uint(AS_(cur, mr + g + 8, kk));
                af[mt][2] = __float_as_uint(AS_(cur, mr + g, kk + 4));
                af[mt][3] = __float_as_uint(AS_(cur, mr + g + 8, kk + 4));
            }
            #pragma unroll
            for (int nt = 0; nt < 4; nt++) {
                int nbk = wn * 4 + nt;
                float2 bf = *(const float2*)&Bs[(((kci * 2) + ks) * 8 + nbk) * 64 + lane * 2];
                unsigned b0 = __float_as_uint(bf.x);
                unsigned b1 = __float_as_uint(bf.y);
                #pragma unroll
                for (int mt = 0; mt < 4; mt++) {
                    asm volatile(
                        "mma.sync.aligned.m16n8k8.row.col.f32.tf32.tf32.f32 "
                        "{%0,%1,%2,%3}, {%4,%5,%6,%7}, {%8,%9}, {%0,%1,%2,%3};"
                        : "+f"(c[mt][nt][0]), "+f"(c[mt][nt][1]),
                          "+f"(c[mt][nt][2]), "+f"(c[mt][nt][3])
                        : "r"(af[mt][0]), "r"(af[mt][1]), "r"(af[mt][2]), "r"(af[mt][3]),
                          "r"(b0), "r"(b1));
                }
            }
        }

        if (kci < 7) {
            #pragma unroll
            for (int p = 0; p < 4; p++)
                *(float4*)&AS_(cur ^ 1, p * 64 + frow, fc) = to_tf32_4(pf[p]);
        }
        __syncthreads();
    }

    int n0 = nb * 64;
    float* outp = (nb == 0) ? g_self : (nb == 1) ? g_bsum :
                  (nb == 2) ? g_esum : (nb == 3) ? g_bmax : g_emax;
    #pragma unroll
    for (int mt = 0; mt < 4; mt++) {
        #pragma unroll
        for (int nt = 0; nt < 4; nt++) {
            int col = wn * 32 + nt * 8 + tig * 2;
            float bx = bias[n0 + col], by = bias[n0 + col + 1];
            int r0 = m0 + wm * 64 + mt * 16 + g;
            if (r0 < NN) {
                float2 o; o.x = c[mt][nt][0] + bx; o.y = c[mt][nt][1] + by;
                *(float2*)&outp[r0 * 64 + col] = o;
            }
            int r1 = r0 + 8;
            if (r1 < NN) {
                float2 o; o.x = c[mt][nt][2] + bx; o.y = c[mt][nt][3] + by;
                *(float2*)&outp[r1 * 64 + col] = o;
            }
        }
    }
    #undef AS_
}

// ---- pass A: per-node segment max + edge-BN stats + global min (2-edge unroll) ----
__global__ void k_edgeA() {
    __shared__ float s_acc[128];
    __shared__ int s_min;
    int tid = threadIdx.x;
    int lane = tid & 31;
    if (tid < 128) s_acc[tid] = 0.0f;
    if (tid == 0) s_min = INT_MAX;
    __syncthreads();

    int warp = (blockIdx.x * blockDim.x + tid) >> 5;
    int nwarp = (gridDim.x * blockDim.x) >> 5;
    float asx = 0.f, asy = 0.f, aqx = 0.f, aqy = 0.f;
    float lmin = INFINITY;

    for (int n = warp; n < NN; n += nwarp) {
        int beg = d_row[n], end = d_row[n + 1];
        float2 bs = *(const float2*)&g_bsum[n * 64 + 2 * lane];
        float2 bm = *(const float2*)&g_bmax[n * 64 + 2 * lane];
        float mx = -INFINITY, my = -INFINITY;
        int e = beg;
        for (; e + 1 < end; e += 2) {
            int ei0 = d_ei[e], ei1 = d_ei[e + 1];
            float2 es0 = *(const float2*)&g_esum[ei0 * 64 + 2 * lane];
            float2 em0 = *(const float2*)&g_emax[ei0 * 64 + 2 * lane];
            float2 es1 = *(const float2*)&g_esum[ei1 * 64 + 2 * lane];
            float2 em1 = *(const float2*)&g_emax[ei1 * 64 + 2 * lane];
            float sx0 = bs.x + es0.x, sy0 = bs.y + es0.y;
            float sx1 = bs.x + es1.x, sy1 = bs.y + es1.y;
            asx += sx0 + sx1; asy += sy0 + sy1;
            aqx += sx0 * sx0 + sx1 * sx1;
            aqy += sy0 * sy0 + sy1 * sy1;
            float m0x = bm.x + em0.x, m0y = bm.y + em0.y;
            float m1x = bm.x + em1.x, m1y = bm.y + em1.y;
            mx = fmaxf(mx, fmaxf(m0x, m1x));
            my = fmaxf(my, fmaxf(m0y, m1y));
            lmin = fminf(lmin, fminf(fminf(m0x, m0y), fminf(m1x, m1y)));
        }
        if (e < end) {
            int ei0 = d_ei[e];
            float2 es0 = *(const float2*)&g_esum[ei0 * 64 + 2 * lane];
            float2 em0 = *(const float2*)&g_emax[ei0 * 64 + 2 * lane];
            float sx0 = bs.x + es0.x, sy0 = bs.y + es0.y;
            asx += sx0; asy += sy0;
            aqx += sx0 * sx0; aqy += sy0 * sy0;
            float m0x = bm.x + em0.x, m0y = bm.y + em0.y;
            mx = fmaxf(mx, m0x);
            my = fmaxf(my, m0y);
            lmin = fminf(lmin, fminf(m0x, m0y));
        }
        float2 o; o.x = mx; o.y = my;
        *(float2*)&g_segmax[n * 64 + 2 * lane] = o;
    }

    atomicAdd(&s_acc[2 * lane], asx);
    atomicAdd(&s_acc[2 * lane + 1], asy);
    atomicAdd(&s_acc[64 + 2 * lane], aqx);
    atomicAdd(&s_acc[64 + 2 * lane + 1], aqy);
    #pragma unroll
    for (int off = 16; off; off >>= 1)
        lmin = fminf(lmin, __shfl_xor_sync(0xffffffffu, lmin, off));
    if (lane == 0) atomicMin(&s_min, fkey(lmin));
    __syncthreads();
    if (tid < 64) {
        atomicAdd(&d_sum_s[tid], s_acc[tid]);
        atomicAdd(&d_ss_s[tid], s_acc[64 + tid]);
    }
    if (tid == 0) atomicMin(&d_min_i, s_min);
}

// ---- pass B: relu(bn(ef_sum)) per-node sum + node-BN stats (sumagg half) ----
__global__ void k_edgeB(const float* __restrict__ gamma,
                        const float* __restrict__ beta) {
    __shared__ float s_acc[128];
    int tid = threadIdx.x;
    int lane = tid & 31;
    if (tid < 128) s_acc[tid] = 0.0f;
    __syncthreads();

    int f0 = 2 * lane, f1 = 2 * lane + 1;
    float mux = d_sum_s[f0] / (float)NE;
    float muy = d_sum_s[f1] / (float)NE;
    float isx = rsqrtf(d_ss_s[f0] / (float)NE - mux * mux + 1e-5f);
    float isy = rsqrtf(d_ss_s[f1] / (float)NE - muy * muy + 1e-5f);
    float ax = isx * gamma[f0], ay = isy * gamma[f1];
    float cx = beta[f0] - mux * ax, cy = beta[f1] - muy * ay;

    int warp = (blockIdx.x * blockDim.x + tid) >> 5;
    int nwarp = (gridDim.x * blockDim.x) >> 5;
    float nsx = 0.f, nsy = 0.f, nqx = 0.f, nqy = 0.f;

    for (int n = warp; n < NN; n += nwarp) {
        int beg = d_row[n], end = d_row[n + 1];
        float2 bs = *(const float2*)&g_bsum[n * 64 + f0];
        float accx = 0.f, accy = 0.f;
        int e = beg;
        for (; e + 1 < end; e += 2) {
            int ei0 = d_ei[e], ei1 = d_ei[e + 1];
            float2 es0 = *(const float2*)&g_esum[ei0 * 64 + f0];
            float2 es1 = *(const float2*)&g_esum[ei1 * 64 + f0];
            accx += fmaxf(0.f, fmaf(bs.x + es0.x, ax, cx))
                  + fmaxf(0.f, fmaf(bs.x + es1.x, ax, cx));
            accy += fmaxf(0.f, fmaf(bs.y + es0.y, ay, cy))
                  + fmaxf(0.f, fmaf(bs.y + es1.y, ay, cy));
        }
        if (e < end) {
            int ei0 = d_ei[e];
            float2 es0 = *(const float2*)&g_esum[ei0 * 64 + f0];
            accx += fmaxf(0.f, fmaf(bs.x + es0.x, ax, cx));
            accy += fmaxf(0.f, fmaf(bs.y + es0.y, ay, cy));
        }
        float2 o; o.x = accx; o.y = accy;
        *(float2*)&g_sumagg[n * 64 + f0] = o;
        nsx += accx; nsy += accy;
        nqx += accx * accx; nqy += accy * accy;
    }

    atomicAdd(&s_acc[f0], nsx);
    atomicAdd(&s_acc[f1], nsy);
    atomicAdd(&s_acc[64 + f0], nqx);
    atomicAdd(&s_acc[64 + f1], nqy);
    __syncthreads();
    if (tid < 64) {
        atomicAdd(&d_sum_g[64 + tid], s_acc[tid]);
        atomicAdd(&d_ss_g[64 + tid], s_acc[64 + tid]);
    }
}

// ---- K5: empty-segment fix + node-BN stats for segmax half ----
__global__ void k_node() {
    __shared__ float s_acc[128];
    int tid = threadIdx.x;
    int lane = tid & 31;
    if (tid < 128) s_acc[tid] = 0.0f;
    __syncthreads();

    int f0 = 2 * lane;
    float minv = fdec(d_min_i);
    int warp = (blockIdx.x * blockDim.x + tid) >> 5;
    int nwarp = (gridDim.x * blockDim.x) >> 5;
    float nsx = 0.f, nsy = 0.f, nqx = 0.f, nqy = 0.f;
    for (int n = warp; n < NN; n += nwarp) {
        float2 v = *(const float2*)&g_segmax[n * 64 + f0];
        if (v.x == -INFINITY) {
            v.x = minv; v.y = minv;
            *(float2*)&g_segmax[n * 64 + f0] = v;
        }
        nsx += v.x; nsy += v.y;
        nqx += v.x * v.x; nqy += v.y * v.y;
    }
    atomicAdd(&s_acc[f0], nsx);
    atomicAdd(&s_acc[f0 + 1], nsy);
    atomicAdd(&s_acc[64 + f0], nqx);
    atomicAdd(&s_acc[64 + f0 + 1], nqy);
    __syncthreads();
    if (tid < 64) {
        atomicAdd(&d_sum_g[tid], s_acc[tid]);
        atomicAdd(&d_ss_g[tid], s_acc[64 + tid]);
    }
}

// ---- K6: finalize node-BN: a, c, doff only (W pack moved to k_prepW) ----
__global__ void k_fin_g(const float* __restrict__ gamma_u,
                        const float* __restrict__ beta_u,
                        const float* __restrict__ W_u) {
    int t = threadIdx.x;  // 128
    float mu = d_sum_g[t] / (float)NN;
    float var = d_ss_g[t] / (float)NN - mu * mu;
    float a = rsqrtf(var + 1e-5f) * gamma_u[t];
    d_a_g[t] = a;
    d_c_g[t] = beta_u[t] - mu * a;
    __syncthreads();
    if (t < 64) {
        float acc = 0.f;
        for (int k = 0; k < 128; k++) acc += d_c_g[k] * W_u[k * 64 + t];
        d_doff[t] = acc;
    }
}

// ---- K7: GEMM2 tf32 mma: out = self + relu((G∘a) @ W + doff), W in smem ----
// dynamic smem: [0,10240) As, [10240,18432) Ws
__global__ void __launch_bounds__(256, 2)
k_final(float* __restrict__ out) {
    extern __shared__ __align__(16) float sm[];
    float* AsB = sm;
    float* Ws  = sm + 10240;
    #define AS_(c, r, k) AsB[(c) * 5120 + (r) * 20 + (k)]

    int tid = threadIdx.x;
    int lane = tid & 31, wid = tid >> 5;
    int wm = wid & 3, wn = wid >> 2;
    int g = lane >> 2, tig = lane & 3;
    int m0 = blockIdx.x * 256;

    float c[4][4][4];
    #pragma unroll
    for (int mt = 0; mt < 4; mt++)
        #pragma unroll
        for (int nt = 0; nt < 4; nt++)
            #pragma unroll
            for (int i = 0; i < 4; i++) c[mt][nt][i] = 0.0f;

    int frow = tid >> 2;
    int fc = (tid & 3) * 4;

    // cooperative copy of packed raw W (8192 floats)
    {
        const float4* src = (const float4*)d_W2;
        float4* dst = (float4*)Ws;
        #pragma unroll
        for (int i = 0; i < 8; i++) dst[tid + i * 256] = src[tid + i * 256];
    }

    // initial fill: k = fc (segmax region), scale by a[k]
    {
        float4 av = *(const float4*)&d_a_g[fc];
        #pragma unroll
        for (int p = 0; p < 4; p++) {
            int gm = m0 + p * 64 + frow;
            float4 v = make_float4(0.f, 0.f, 0.f, 0.f);
            if (gm < NN) v = *(const float4*)&g_segmax[gm * 64 + fc];
            v.x *= av.x; v.y *= av.y; v.z *= av.z; v.w *= av.w;
            *(float4*)&AS_(0, p * 64 + frow, fc) = to_tf32_4(v);
        }
    }
    __syncthreads();

    #pragma unroll
    for (int kci = 0; kci < 8; kci++) {
        int cur = kci & 1;
        float4 pf[4];
        float4 av;
        if (kci < 7) {
            int kg = (kci + 1) * 16 + fc;
            const float* src = (kg < 64) ? g_segmax : g_sumagg;
            int off = (kg < 64) ? kg : (kg - 64);
            av = *(const float4*)&d_a_g[kg];
            #pragma unroll
            for (int p = 0; p < 4; p++) {
                int gm = m0 + p * 64 + frow;
                pf[p] = make_float4(0.f, 0.f, 0.f, 0.f);
                if (gm < NN) pf[p] = *(const float4*)&src[gm * 64 + off];
            }
        }

        #pragma unroll
        for (int ks = 0; ks < 2; ks++) {
            int kk = ks * 8 + tig;
            unsigned af[4][4];
            #pragma unroll
            for (int mt = 0; mt < 4; mt++) {
                int mr = wm * 64 + mt * 16;
                af[mt][0] = __float_as_uint(AS_(cur, mr + g, kk));
                af[mt][1] = __float_as_uint(AS_(cur, mr + g + 8, kk));
                af[mt][2] = __float_as_uint(AS_(cur, mr + g, kk + 4));
                af[mt][3] = __float_as_uint(AS_(cur, mr + g + 8, kk + 4));
            }
            #pragma unroll
            for (int nt = 0; nt < 4; nt++) {
                int nbk = wn * 4 + nt;
                float2 bf = *(const float2*)&Ws[(((kci * 2) + ks) * 8 + nbk) * 64 + lane * 2];
                unsigned b0 = __float_as_uint(bf.x);
                unsigned b1 = __float_as_uint(bf.y);
                #pragma unroll
                for (int mt = 0; mt < 4; mt++) {
                    asm volatile(
                        "mma.sync.aligned.m16n8k8.row.col.f32.tf32.tf32.f32 "
                        "{%0,%1,%2,%3}, {%4,%5,%6,%7}, {%8,%9}, {%0,%1,%2,%3};"
                        : "+f"(c[mt][nt][0]), "+f"(c[mt][nt][1]),
                          "+f"(c[mt][nt][2]), "+f"(c[mt][nt][3])
                        : "r"(af[mt][0]), "r"(af[mt][1]), "r"(af[mt][2]), "r"(af[mt][3]),
                          "r"(b0), "r"(b1));
                }
            }
        }

        if (kci < 7) {
            #pragma unroll
            for (int p = 0; p < 4; p++) {
                float4 v = pf[p];
                v.x *= av.x; v.y *= av.y; v.z *= av.z; v.w *= av.w;
                *(float4*)&AS_(cur ^ 1, p * 64 + frow, fc) = to_tf32_4(v);
            }
        }
        __syncthreads();
    }

    #pragma unroll
    for (int mt = 0; mt < 4; mt++) {
        #pragma unroll
        for (int nt = 0; nt < 4; nt++) {
            int col = wn * 32 + nt * 8 + tig * 2;
            float dx = d_doff[col], dy = d_doff[col + 1];
            int r0 = m0 + wm * 64 + mt * 16 + g;
            if (r0 < NN) {
                float2 sf = *(const float2*)&g_self[r0 * 64 + col];
                float2 o;
                o.x = sf.x + fmaxf(0.f, c[mt][nt][0] + dx);
                o.y = sf.y + fmaxf(0.f, c[mt][nt][1] + dy);
                *(float2*)&out[r0 * 64 + col] = o;
            }
            int r1 = r0 + 8;
            if (r1 < NN) {
                float2 sf = *(const float2*)&g_self[r1 * 64 + col];
                float2 o;
                o.x = sf.x + fmaxf(0.f, c[mt][nt][2] + dx);
                o.y = sf.y + fmaxf(0.f, c[mt][nt][3] + dy);
                *(float2*)&out[r1 * 64 + col] = o;
            }
        }
    }
    #undef AS_
}

extern "C" void kernel_launch(void* const* d_in, const int* in_sizes, int n_in,
                              void* d_out, int out_size) {
    const float* n_feat  = (const float*)d_in[0];
    const int*   eidx    = (const int*)d_in[1];
    const float* W_b     = (const float*)d_in[2];
    const float* b_b     = (const float*)d_in[3];
    const float* gamma_g = (const float*)d_in[4];
    const float* beta_g  = (const float*)d_in[5];
    const float* gamma_u = (const float*)d_in[6];
    const float* beta_u  = (const float*)d_in[7];
    const float* W_u     = (const float*)d_in[8];
    float* out           = (float*)d_out;

    const int* begin_ids = eidx;
    const int* end_ids   = eidx + NE;

    static cudaStream_t s1 = 0;
    static cudaEvent_t evFork = 0, evJoin = 0, evFork2 = 0, evJoin2 = 0;
    if (!s1) {
        cudaStreamCreateWithFlags(&s1, cudaStreamNonBlocking);
        cudaEventCreateWithFlags(&evFork, cudaEventDisableTiming);
        cudaEventCreateWithFlags(&evJoin, cudaEventDisableTiming);
        cudaEventCreateWithFlags(&evFork2, cudaEventDisableTiming);
        cudaEventCreateWithFlags(&evJoin2, cudaEventDisableTiming);
        cudaFuncSetAttribute(k_gemm1, cudaFuncAttributeMaxDynamicSharedMemorySize, 73728);
        cudaFuncSetAttribute(k_final, cudaFuncAttributeMaxDynamicSharedMemorySize, 73728);
    }

    // fork: GEMM chain on s1, CSR chain on default stream — independent
    cudaEventRecord(evFork, 0);
    cudaStreamWaitEvent(s1, evFork, 0);
    k_prepB<<<160, 256, 0, s1>>>(W_b);
    k_prepW<<<16, 256, 0, s1>>>(W_u);
    dim3 g1((NN + 255) / 256, 5);
    k_gemm1<<<g1, 256, 73728, s1>>>(n_feat, b_b);

    k_init<<<256, 256>>>();
    k_deg<<<1184, 256>>>(begin_ids);
    k_scan1<<<NBLK, SCAN_B>>>();
    k_scan3<<<NBLK, SCAN_B>>>();
    k_fill<<<1184, 256>>>(begin_ids, end_ids);

    // join: edgeA needs GEMM outputs and CSR
    cudaEventRecord(evJoin, s1);
    cudaStreamWaitEvent(0, evJoin, 0);
    k_edgeA<<<1184, 256>>>();

    // fork 2: k_node (needs only edgeA) overlaps edgeB (disjoint d_sum_g halves)
    cudaEventRecord(evFork2, 0);
    cudaStreamWaitEvent(s1, evFork2, 0);
    k_node<<<1184, 256, 0, s1>>>();

    k_edgeB<<<1184, 256>>>(gamma_g, beta_g);

    cudaEventRecord(evJoin2, s1);
    cudaStreamWaitEvent(0, evJoin2, 0);
    k_fin_g<<<1, 128>>>(gamma_u, beta_u, W_u);
    k_final<<<(NN + 255) / 256, 256, 73728>>>(out);
}